// round 1
// baseline (speedup 1.0000x reference)
#include <cuda_runtime.h>
#include <math.h>

// Problem constants
#define Bb 8
#define Ss 1024
#define Dd 1024
#define Hh 8
#define DKk 128
#define FFf 4096
#define Ll 2

// ---------------- scratch (device globals; no allocation allowed) ----------
__device__ float g_x [Bb*Ss*Dd];
__device__ float g_y [Bb*Ss*Dd];
__device__ float g_k [Bb*Ss*Dd];
__device__ float g_v [Bb*Ss*Dd];
__device__ float g_t1[Bb*Ss*Dd];
__device__ float g_t2[Bb*Ss*Dd];
__device__ float g_ff[Bb*Ss*FFf];
__device__ float g_sc[(size_t)Bb*Hh*Ss*Ss];   // 256 MB score scratch

// ---------------- elementwise: x = q + pe, y = qa + pe ---------------------
__global__ void add_pos_kernel(const float* __restrict__ q,
                               const float* __restrict__ qa,
                               const float* __restrict__ pe,
                               float* __restrict__ x,
                               float* __restrict__ y)
{
    int idx = blockIdx.x * 256 + threadIdx.x;       // total B*S*D = 8388608
    int sd  = idx & (Ss*Dd - 1);                    // S*D = 1<<20
    float p = pe[sd];
    x[idx] = q[idx]  + p;
    y[idx] = qa[idx] + p;
}

// ---------------- tiled fp32 GEMM, C = alpha * A * B^T (+bias)(+relu) ------
// A: [M,K] row-major lda; B: [N,K] row-major ldb; C: [M,N] row-major ldc.
// Batched via blockIdx.z with split index z = zb*bdiv + zh and per-operand
// strides (covers per-(b,h) attention slices). All dims multiples of tile.
__global__ void __launch_bounds__(256, 2)
gemm_nt(const float* __restrict__ A, int lda,
        const float* __restrict__ B, int ldb,
        const float* __restrict__ bias,
        float* __restrict__ C, int ldc,
        int K, int bdiv,
        long sA0, long sA1, long sB0, long sB1, long sC0, long sC1,
        float alpha, int relu)
{
    __shared__ float As[8][128];
    __shared__ float Bs[8][128];

    int z  = blockIdx.z;
    int zb = z / bdiv, zh = z - zb * bdiv;
    A += zb * sA0 + zh * sA1;
    B += zb * sB0 + zh * sB1;
    C += zb * sC0 + zh * sC1;

    const int tid = threadIdx.x;
    const int m0 = blockIdx.y * 128, n0 = blockIdx.x * 128;
    const int lr = tid >> 1, lk = (tid & 1) * 4;    // 128 rows x 8 k per tile
    const int ty = tid >> 4, tx = tid & 15;

    const float* Ap = A + (long)(m0 + lr) * lda + lk;
    const float* Bp = B + (long)(n0 + lr) * ldb + lk;

    float acc[8][8] = {};
    for (int k0 = 0; k0 < K; k0 += 8) {
        float4 a4 = *(const float4*)(Ap + k0);
        float4 b4 = *(const float4*)(Bp + k0);
        __syncthreads();
        As[lk+0][lr] = a4.x; As[lk+1][lr] = a4.y; As[lk+2][lr] = a4.z; As[lk+3][lr] = a4.w;
        Bs[lk+0][lr] = b4.x; Bs[lk+1][lr] = b4.y; Bs[lk+2][lr] = b4.z; Bs[lk+3][lr] = b4.w;
        __syncthreads();
#pragma unroll
        for (int kk = 0; kk < 8; kk++) {
            float a[8], b[8];
#pragma unroll
            for (int i = 0; i < 8; i++) a[i] = As[kk][ty*8+i];
#pragma unroll
            for (int j = 0; j < 8; j++) b[j] = Bs[kk][tx*8+j];
#pragma unroll
            for (int i = 0; i < 8; i++)
#pragma unroll
                for (int j = 0; j < 8; j++)
                    acc[i][j] += a[i] * b[j];
        }
    }

#pragma unroll
    for (int i = 0; i < 8; i++) {
        long m = m0 + ty*8 + i;
#pragma unroll
        for (int j = 0; j < 8; j += 4) {
            int n = n0 + tx*8 + j;
            float4 o;
            o.x = acc[i][j+0] * alpha;
            o.y = acc[i][j+1] * alpha;
            o.z = acc[i][j+2] * alpha;
            o.w = acc[i][j+3] * alpha;
            if (bias) {
                o.x += bias[n+0]; o.y += bias[n+1];
                o.z += bias[n+2]; o.w += bias[n+3];
            }
            if (relu) {
                o.x = fmaxf(o.x, 0.f); o.y = fmaxf(o.y, 0.f);
                o.z = fmaxf(o.z, 0.f); o.w = fmaxf(o.w, 0.f);
            }
            *(float4*)(C + m * ldc + n) = o;
        }
    }
}

// ---------------- tiled fp32 GEMM, C = A * B (NN) --------------------------
// A: [M,K] lda; B: [K,N] ldb; C: [M,N] ldc. Used for attn @ V.
__global__ void __launch_bounds__(256, 2)
gemm_nn(const float* __restrict__ A, int lda,
        const float* __restrict__ B, int ldb,
        float* __restrict__ C, int ldc,
        int K, int bdiv,
        long sA0, long sA1, long sB0, long sB1, long sC0, long sC1)
{
    __shared__ float As[8][128];
    __shared__ float Bs[8][128];

    int z  = blockIdx.z;
    int zb = z / bdiv, zh = z - zb * bdiv;
    A += zb * sA0 + zh * sA1;
    B += zb * sB0 + zh * sB1;
    C += zb * sC0 + zh * sC1;

    const int tid = threadIdx.x;
    const int m0 = blockIdx.y * 128, n0 = blockIdx.x * 128;
    const int lr = tid >> 1, lk = (tid & 1) * 4;    // A tile: 128 x 8
    const int kr = tid >> 5, nc = (tid & 31) * 4;   // B tile: 8 x 128
    const int ty = tid >> 4, tx = tid & 15;

    const float* Ap = A + (long)(m0 + lr) * lda + lk;
    const float* Bp = B + (long)kr * ldb + n0 + nc;

    float acc[8][8] = {};
    for (int k0 = 0; k0 < K; k0 += 8) {
        float4 a4 = *(const float4*)(Ap + k0);
        float4 b4 = *(const float4*)(Bp + (long)k0 * ldb);
        __syncthreads();
        As[lk+0][lr] = a4.x; As[lk+1][lr] = a4.y; As[lk+2][lr] = a4.z; As[lk+3][lr] = a4.w;
        *(float4*)&Bs[kr][nc] = b4;
        __syncthreads();
#pragma unroll
        for (int kk = 0; kk < 8; kk++) {
            float a[8], b[8];
#pragma unroll
            for (int i = 0; i < 8; i++) a[i] = As[kk][ty*8+i];
#pragma unroll
            for (int j = 0; j < 8; j++) b[j] = Bs[kk][tx*8+j];
#pragma unroll
            for (int i = 0; i < 8; i++)
#pragma unroll
                for (int j = 0; j < 8; j++)
                    acc[i][j] += a[i] * b[j];
        }
    }

#pragma unroll
    for (int i = 0; i < 8; i++) {
        long m = m0 + ty*8 + i;
#pragma unroll
        for (int j = 0; j < 8; j += 4) {
            int n = n0 + tx*8 + j;
            float4 o;
            o.x = acc[i][j+0]; o.y = acc[i][j+1];
            o.z = acc[i][j+2]; o.w = acc[i][j+3];
            *(float4*)(C + m * ldc + n) = o;
        }
    }
}

// ---------------- causal masked softmax, in place on scores ----------------
// One block per (b,h,i) row. Allowed keys: j < i. Row 0 -> all zeros
// (matches reference zero_pad of the first query row).
__global__ void softmax_rows(float* __restrict__ sc)
{
    __shared__ float red[256];
    long row = blockIdx.x;
    int  i   = (int)(row & (Ss - 1));
    float* p = sc + row * (long)Ss;
    int tid  = threadIdx.x;

    if (i == 0) {
        for (int j = tid; j < Ss; j += 256) p[j] = 0.f;
        return;
    }

    float mx = -3.4e38f;
    for (int j = tid; j < i; j += 256) mx = fmaxf(mx, p[j]);
    red[tid] = mx; __syncthreads();
    for (int off = 128; off > 0; off >>= 1) {
        if (tid < off) red[tid] = fmaxf(red[tid], red[tid + off]);
        __syncthreads();
    }
    mx = red[0]; __syncthreads();

    float s = 0.f;
    for (int j = tid; j < i; j += 256) s += expf(p[j] - mx);
    red[tid] = s; __syncthreads();
    for (int off = 128; off > 0; off >>= 1) {
        if (tid < off) red[tid] += red[tid + off];
        __syncthreads();
    }
    float inv = 1.f / red[0];

    for (int j = tid; j < Ss; j += 256)
        p[j] = (j < i) ? expf(p[j] - mx) * inv : 0.f;
}

// ---------------- residual add + LayerNorm ---------------------------------
// out[row] = LN(x[row] + t[row]) * g + b.  One block per row, D=1024.
__global__ void ln_res(const float* __restrict__ x, const float* __restrict__ t,
                       const float* __restrict__ g, const float* __restrict__ b,
                       float* __restrict__ out)
{
    __shared__ float red[256];
    long row = blockIdx.x;
    int tid = threadIdx.x;
    const float* xp = x + row * Dd;
    const float* tp = t + row * Dd;

    float v[4];
    float s = 0.f;
#pragma unroll
    for (int q = 0; q < 4; q++) {
        int c = tid + q * 256;
        v[q] = xp[c] + tp[c];
        s += v[q];
    }
    red[tid] = s; __syncthreads();
    for (int off = 128; off > 0; off >>= 1) {
        if (tid < off) red[tid] += red[tid + off];
        __syncthreads();
    }
    float mean = red[0] * (1.f / Dd);
    __syncthreads();

    float s2 = 0.f;
#pragma unroll
    for (int q = 0; q < 4; q++) {
        float d = v[q] - mean;
        s2 += d * d;
    }
    red[tid] = s2; __syncthreads();
    for (int off = 128; off > 0; off >>= 1) {
        if (tid < off) red[tid] += red[tid + off];
        __syncthreads();
    }
    float inv = rsqrtf(red[0] * (1.f / Dd) + 1e-5f);

#pragma unroll
    for (int q = 0; q < 4; q++) {
        int c = tid + q * 256;
        out[row * Dd + c] = (v[q] - mean) * inv * g[c] + b[c];
    }
}

// ---------------- driver ----------------------------------------------------
extern "C" void kernel_launch(void* const* d_in, const int* in_sizes, int n_in,
                              void* d_out, int out_size)
{
    const float* q_embed = (const float*)d_in[0];
    const float* qa_embed= (const float*)d_in[1];
    const float* pos     = (const float*)d_in[2];
    const float* Wk  = (const float*)d_in[3];
    const float* bk  = (const float*)d_in[4];
    const float* Wv  = (const float*)d_in[5];
    const float* bv  = (const float*)d_in[6];
    const float* Wo  = (const float*)d_in[7];
    const float* bo  = (const float*)d_in[8];
    const float* ln1g= (const float*)d_in[9];
    const float* ln1b= (const float*)d_in[10];
    const float* W1  = (const float*)d_in[11];
    const float* b1  = (const float*)d_in[12];
    const float* W2  = (const float*)d_in[13];
    const float* b2  = (const float*)d_in[14];
    const float* ln2g= (const float*)d_in[15];
    const float* ln2b= (const float*)d_in[16];
    float* out = (float*)d_out;

    float *x, *y, *k, *v, *t1, *t2, *ff, *sc;
    cudaGetSymbolAddress((void**)&x,  g_x);
    cudaGetSymbolAddress((void**)&y,  g_y);
    cudaGetSymbolAddress((void**)&k,  g_k);
    cudaGetSymbolAddress((void**)&v,  g_v);
    cudaGetSymbolAddress((void**)&t1, g_t1);
    cudaGetSymbolAddress((void**)&t2, g_t2);
    cudaGetSymbolAddress((void**)&ff, g_ff);
    cudaGetSymbolAddress((void**)&sc, g_sc);

    add_pos_kernel<<<(Bb*Ss*Dd)/256, 256>>>(q_embed, qa_embed, pos, x, y);

    const float inv_sqrt_dk = 0.08838834764831845f;  // 1/sqrt(128)

    for (int l = 0; l < Ll; l++) {
        const float* Wkl = Wk + (long)l*Dd*Dd;  const float* bkl = bk + (long)l*Dd;
        const float* Wvl = Wv + (long)l*Dd*Dd;  const float* bvl = bv + (long)l*Dd;
        const float* Wol = Wo + (long)l*Dd*Dd;  const float* bol = bo + (long)l*Dd;
        const float* W1l = W1 + (long)l*FFf*Dd; const float* b1l = b1 + (long)l*FFf;
        const float* W2l = W2 + (long)l*Dd*FFf; const float* b2l = b2 + (long)l*Dd;

        dim3 gP(Dd/128,  (Bb*Ss)/128, 1);   // projections: 8192x1024x1024
        dim3 gS(Ss/128,  Ss/128,  Bb*Hh);   // scores: 1024x1024x128 per (b,h)
        dim3 gA(DKk/128, Ss/128,  Bb*Hh);   // attn@V: 1024x128x1024 per (b,h)
        dim3 gF1(FFf/128,(Bb*Ss)/128, 1);   // FF1: 8192x4096x1024
        dim3 gF2(Dd/128, (Bb*Ss)/128, 1);   // FF2: 8192x1024x4096

        // K = x @ Wk^T + bk   (q == k in this model)
        gemm_nt<<<gP, 256>>>(x, Dd, Wkl, Dd, bkl, k, Dd, Dd, 1,
                             0,0,0,0,0,0, 1.f, 0);
        // V = y @ Wv^T + bv
        gemm_nt<<<gP, 256>>>(y, Dd, Wvl, Dd, bvl, v, Dd, Dd, 1,
                             0,0,0,0,0,0, 1.f, 0);
        // scores[b,h] = (K_bh @ K_bh^T) / sqrt(DK)
        gemm_nt<<<gS, 256>>>(k, Dd, k, Dd, nullptr, sc, Ss, DKk, Hh,
                             (long)Ss*Dd, DKk,
                             (long)Ss*Dd, DKk,
                             (long)Hh*Ss*Ss, (long)Ss*Ss,
                             inv_sqrt_dk, 0);
        // masked softmax (strict causal, row 0 zeroed)
        softmax_rows<<<Bb*Hh*Ss, 256>>>(sc);
        // t1[b,:,h,:] = attn[b,h] @ V_bh
        gemm_nn<<<gA, 256>>>(sc, Ss, v, Dd, t1, Dd, Ss, Hh,
                             (long)Hh*Ss*Ss, (long)Ss*Ss,
                             (long)Ss*Dd, DKk,
                             (long)Ss*Dd, DKk);
        // t2 = t1 @ Wo^T + bo
        gemm_nt<<<gP, 256>>>(t1, Dd, Wol, Dd, bol, t2, Dd, Dd, 1,
                             0,0,0,0,0,0, 1.f, 0);
        // x = LN(x + t2)
        ln_res<<<Bb*Ss, 256>>>(x, t2, ln1g + (long)l*Dd, ln1b + (long)l*Dd, x);
        // ff = relu(x @ W1^T + b1)
        gemm_nt<<<gF1, 256>>>(x, Dd, W1l, Dd, b1l, ff, FFf, Dd, 1,
                              0,0,0,0,0,0, 1.f, 1);
        // t2 = ff @ W2^T + b2
        gemm_nt<<<gF2, 256>>>(ff, FFf, W2l, FFf, b2l, t2, Dd, FFf, 1,
                              0,0,0,0,0,0, 1.f, 0);
        // x = LN(x + t2); final layer writes straight to d_out
        float* xout = (l == Ll - 1) ? out : x;
        ln_res<<<Bb*Ss, 256>>>(x, t2, ln2g + (long)l*Dd, ln2b + (long)l*Dd, xout);
    }
}

// round 3
// speedup vs baseline: 2.5027x; 2.5027x over previous
#include <cuda_runtime.h>
#include <cuda_bf16.h>
#include <math.h>
#include <stdint.h>

// Problem constants
#define Bb 8
#define Ss 1024
#define Dd 1024
#define Hh 8
#define DKk 128
#define FFf 4096
#define Ll 2

// ---------------- scratch (device globals; no allocation allowed) ----------
__device__ float g_x [Bb*Ss*Dd];
__device__ float g_y [Bb*Ss*Dd];
__device__ float g_k [Bb*Ss*Dd];
__device__ float g_v [Bb*Ss*Dd];       // holds vT[b,h,dk,s]
__device__ float g_t1[Bb*Ss*Dd];
__device__ float g_t2[Bb*Ss*Dd];
__device__ float g_ff[Bb*Ss*FFf];
__device__ float g_sc[(size_t)Bb*Hh*Ss*Ss];   // 256 MB score scratch

// ======================= helpers ============================================
__device__ __forceinline__ uint32_t smem_u32(const void* p) {
    uint32_t a;
    asm("{ .reg .u64 t; cvta.to.shared.u64 t, %1; cvt.u32.u64 %0, t; }"
        : "=r"(a) : "l"(p));
    return a;
}

__device__ __forceinline__ void ldsm4(uint32_t* r, uint32_t addr) {
    asm volatile("ldmatrix.sync.aligned.m8n8.x4.shared.b16 {%0,%1,%2,%3}, [%4];"
        : "=r"(r[0]), "=r"(r[1]), "=r"(r[2]), "=r"(r[3]) : "r"(addr));
}

__device__ __forceinline__ void mma16816(float* c, const uint32_t* a,
                                         const uint32_t* b) {
    asm volatile(
        "mma.sync.aligned.m16n8k16.row.col.f32.bf16.bf16.f32 "
        "{%0,%1,%2,%3}, {%4,%5,%6,%7}, {%8,%9}, {%0,%1,%2,%3};"
        : "+f"(c[0]), "+f"(c[1]), "+f"(c[2]), "+f"(c[3])
        : "r"(a[0]), "r"(a[1]), "r"(a[2]), "r"(a[3]), "r"(b[0]), "r"(b[1]));
}

__device__ __forceinline__ void sts64(uint32_t addr, uint32_t w0, uint32_t w1) {
    asm volatile("st.shared.v2.b32 [%0], {%1,%2};"
        :: "r"(addr), "r"(w0), "r"(w1) : "memory");
}

__device__ __forceinline__ uint32_t pack_bf16(__nv_bfloat16 a, __nv_bfloat16 b) {
    return (uint32_t)__bfloat16_as_ushort(b) << 16 | __bfloat16_as_ushort(a);
}

// ---------------- elementwise: x = q + pe, y = qa + pe ---------------------
__global__ void add_pos_kernel(const float* __restrict__ q,
                               const float* __restrict__ qa,
                               const float* __restrict__ pe,
                               float* __restrict__ x,
                               float* __restrict__ y)
{
    int idx = blockIdx.x * 256 + threadIdx.x;
    int sd  = idx & (Ss*Dd - 1);
    float p = pe[sd];
    x[idx] = q[idx]  + p;
    y[idx] = qa[idx] + p;
}

// ============ HMMA bf16x3 GEMM: C = alpha * A * B^T (+bias)(+relu) =========
// A: [M,K] row-major lda; B: [N,K] row-major ldb; C: [M,N] ldc.
// bf16x3 split (AhiBhi + AloBhi + AhiBlo, fp32 accum) ~= fp32 precision.
// Tile 128x128, K staged 32 wide. Batched via blockIdx.z (z = zb*bdiv + zh).
// transV: scatter-store output as vT[b,h,dk,s] (for the V projection).
#define ROWB 80                        // SMEM row stride in bytes (32 bf16 + pad)
#define TILE_BYTES (128 * ROWB)        // 10240 per hi/lo per matrix
#define SM_AHI 0
#define SM_ALO TILE_BYTES
#define SM_BHI (2 * TILE_BYTES)
#define SM_BLO (3 * TILE_BYTES)
#define DSMEM_BYTES (4 * TILE_BYTES)

__global__ void __launch_bounds__(256, 2)
gemm_mma(const float* __restrict__ A, int lda,
         const float* __restrict__ B, int ldb,
         const float* __restrict__ bias,
         float* __restrict__ C, int ldc,
         int K, int bdiv,
         long sA0, long sA1, long sB0, long sB1, long sC0, long sC1,
         float alpha, int relu, int transV)
{
    extern __shared__ char dsm[];
    uint32_t sb = smem_u32(dsm);

    int z  = blockIdx.z;
    int zb = z / bdiv, zh = z - zb * bdiv;
    A += zb * sA0 + zh * sA1;
    B += zb * sB0 + zh * sB1;
    C += zb * sC0 + zh * sC1;

    const int m0 = blockIdx.y * 128, n0 = blockIdx.x * 128;
    const int tid  = threadIdx.x;
    const int lane = tid & 31, wid = tid >> 5;
    const int mW = (wid >> 1) * 32, nW = (wid & 1) * 64;

    // gmem->smem writer lanes: each thread owns 16 floats of one row per matrix
    const int wr = tid >> 1, wc = (tid & 1) * 16;
    const float* pA = A + (long)(m0 + wr) * lda + wc;
    const float* pB = B + (long)(n0 + wr) * ldb + wc;
    const uint32_t wOff = (uint32_t)(wr * ROWB + wc * 2);

    // ldmatrix source addresses
    const uint32_t aRowOff = (uint32_t)((mW + (lane & 15)) * ROWB + (lane >> 4) * 16);
    const uint32_t bRowOff = (uint32_t)((nW + (lane & 7) + ((lane >> 4) * 8)) * ROWB
                                        + ((lane >> 3) & 1) * 16);

    float acc[2][8][4] = {};

    const int nst = K >> 5;
    for (int st = 0; st < nst; st++) {
        const int k0 = st * 32;
        // ---- load + split + store (A and B) ----
        {
            float4 fa[4], fb[4];
#pragma unroll
            for (int i = 0; i < 4; i++) fa[i] = *(const float4*)(pA + k0 + i*4);
#pragma unroll
            for (int i = 0; i < 4; i++) fb[i] = *(const float4*)(pB + k0 + i*4);
            __syncthreads();   // prev compute done before overwriting smem
#pragma unroll
            for (int i = 0; i < 4; i++) {
                float4 f = fa[i];
                __nv_bfloat16 h0=__float2bfloat16(f.x), h1=__float2bfloat16(f.y);
                __nv_bfloat16 h2=__float2bfloat16(f.z), h3=__float2bfloat16(f.w);
                __nv_bfloat16 l0=__float2bfloat16(f.x-__bfloat162float(h0));
                __nv_bfloat16 l1=__float2bfloat16(f.y-__bfloat162float(h1));
                __nv_bfloat16 l2=__float2bfloat16(f.z-__bfloat162float(h2));
                __nv_bfloat16 l3=__float2bfloat16(f.w-__bfloat162float(h3));
                sts64(sb + SM_AHI + wOff + i*8, pack_bf16(h0,h1), pack_bf16(h2,h3));
                sts64(sb + SM_ALO + wOff + i*8, pack_bf16(l0,l1), pack_bf16(l2,l3));
            }
#pragma unroll
            for (int i = 0; i < 4; i++) {
                float4 f = fb[i];
                __nv_bfloat16 h0=__float2bfloat16(f.x), h1=__float2bfloat16(f.y);
                __nv_bfloat16 h2=__float2bfloat16(f.z), h3=__float2bfloat16(f.w);
                __nv_bfloat16 l0=__float2bfloat16(f.x-__bfloat162float(h0));
                __nv_bfloat16 l1=__float2bfloat16(f.y-__bfloat162float(h1));
                __nv_bfloat16 l2=__float2bfloat16(f.z-__bfloat162float(h2));
                __nv_bfloat16 l3=__float2bfloat16(f.w-__bfloat162float(h3));
                sts64(sb + SM_BHI + wOff + i*8, pack_bf16(h0,h1), pack_bf16(h2,h3));
                sts64(sb + SM_BLO + wOff + i*8, pack_bf16(l0,l1), pack_bf16(l2,l3));
            }
        }
        __syncthreads();

        // ---- compute: 2 k16 steps ----
#pragma unroll
        for (int kk = 0; kk < 2; kk++) {
            const uint32_t kb = kk * 32;   // 16 bf16 = 32 bytes
            uint32_t Ah[2][4], Al[2][4];
            ldsm4(Ah[0], sb + SM_AHI + aRowOff + kb);
            ldsm4(Ah[1], sb + SM_AHI + aRowOff + 16*ROWB + kb);
            ldsm4(Al[0], sb + SM_ALO + aRowOff + kb);
            ldsm4(Al[1], sb + SM_ALO + aRowOff + 16*ROWB + kb);
#pragma unroll
            for (int nh = 0; nh < 4; nh++) {
                uint32_t Bh[4], Bl[4];
                ldsm4(Bh, sb + SM_BHI + bRowOff + nh*16*ROWB + kb);
                ldsm4(Bl, sb + SM_BLO + bRowOff + nh*16*ROWB + kb);
#pragma unroll
                for (int mt = 0; mt < 2; mt++) {
                    mma16816(acc[mt][nh*2+0], Ah[mt], Bh);
                    mma16816(acc[mt][nh*2+0], Al[mt], Bh);
                    mma16816(acc[mt][nh*2+0], Ah[mt], Bl);
                    mma16816(acc[mt][nh*2+1], Ah[mt], Bh+2);
                    mma16816(acc[mt][nh*2+1], Al[mt], Bh+2);
                    mma16816(acc[mt][nh*2+1], Ah[mt], Bl+2);
                }
            }
        }
    }

    // ---- epilogue ----
    const int rIn = lane >> 2, cIn = (lane & 3) * 2;
#pragma unroll
    for (int mt = 0; mt < 2; mt++) {
#pragma unroll
        for (int nt = 0; nt < 8; nt++) {
            float* a4 = acc[mt][nt];
            int col = n0 + nW + nt*8 + cIn;
            long r0 = (long)m0 + mW + mt*16 + rIn;
            long r1 = r0 + 8;
            float v0 = a4[0]*alpha, v1 = a4[1]*alpha;
            float v2 = a4[2]*alpha, v3 = a4[3]*alpha;
            if (bias) {
                float b0_ = bias[col], b1_ = bias[col+1];
                v0 += b0_; v1 += b1_; v2 += b0_; v3 += b1_;
            }
            if (relu) {
                v0 = fmaxf(v0,0.f); v1 = fmaxf(v1,0.f);
                v2 = fmaxf(v2,0.f); v3 = fmaxf(v3,0.f);
            }
            if (!transV) {
                *(float2*)(C + r0*ldc + col) = make_float2(v0, v1);
                *(float2*)(C + r1*ldc + col) = make_float2(v2, v3);
            } else {
                int b0i = (int)(r0 >> 10), s0 = (int)(r0 & 1023);
                int b1i = (int)(r1 >> 10), s1 = (int)(r1 & 1023);
                int h = col >> 7, dk = col & 127;
                C[((long)((b0i*Hh + h)*DKk + dk) << 10) + s0] = v0;
                C[((long)((b0i*Hh + h)*DKk + dk + 1) << 10) + s0] = v1;
                C[((long)((b1i*Hh + h)*DKk + dk) << 10) + s1] = v2;
                C[((long)((b1i*Hh + h)*DKk + dk + 1) << 10) + s1] = v3;
            }
        }
    }
}

// ---------------- causal masked softmax, in place on scores ----------------
__global__ void softmax_rows(float* __restrict__ sc)
{
    __shared__ float red[256];
    long row = blockIdx.x;
    int  i   = (int)(row & (Ss - 1));
    float* p = sc + row * (long)Ss;
    int tid  = threadIdx.x;

    if (i == 0) {
        for (int j = tid; j < Ss; j += 256) p[j] = 0.f;
        return;
    }

    float mx = -3.4e38f;
    for (int j = tid; j < i; j += 256) mx = fmaxf(mx, p[j]);
    red[tid] = mx; __syncthreads();
    for (int off = 128; off > 0; off >>= 1) {
        if (tid < off) red[tid] = fmaxf(red[tid], red[tid + off]);
        __syncthreads();
    }
    mx = red[0]; __syncthreads();

    float s = 0.f;
    for (int j = tid; j < i; j += 256) s += expf(p[j] - mx);
    red[tid] = s; __syncthreads();
    for (int off = 128; off > 0; off >>= 1) {
        if (tid < off) red[tid] += red[tid + off];
        __syncthreads();
    }
    float inv = 1.f / red[0];

    for (int j = tid; j < Ss; j += 256)
        p[j] = (j < i) ? expf(p[j] - mx) * inv : 0.f;
}

// ---------------- residual add + LayerNorm ---------------------------------
__global__ void ln_res(const float* __restrict__ x, const float* __restrict__ t,
                       const float* __restrict__ g, const float* __restrict__ b,
                       float* __restrict__ out)
{
    __shared__ float red[256];
    long row = blockIdx.x;
    int tid = threadIdx.x;
    const float* xp = x + row * Dd;
    const float* tp = t + row * Dd;

    float v[4];
    float s = 0.f;
#pragma unroll
    for (int q = 0; q < 4; q++) {
        int c = tid + q * 256;
        v[q] = xp[c] + tp[c];
        s += v[q];
    }
    red[tid] = s; __syncthreads();
    for (int off = 128; off > 0; off >>= 1) {
        if (tid < off) red[tid] += red[tid + off];
        __syncthreads();
    }
    float mean = red[0] * (1.f / Dd);
    __syncthreads();

    float s2 = 0.f;
#pragma unroll
    for (int q = 0; q < 4; q++) {
        float d = v[q] - mean;
        s2 += d * d;
    }
    red[tid] = s2; __syncthreads();
    for (int off = 128; off > 0; off >>= 1) {
        if (tid < off) red[tid] += red[tid + off];
        __syncthreads();
    }
    float inv = rsqrtf(red[0] * (1.f / Dd) + 1e-5f);

#pragma unroll
    for (int q = 0; q < 4; q++) {
        int c = tid + q * 256;
        out[row * Dd + c] = (v[q] - mean) * inv * g[c] + b[c];
    }
}

// ---------------- driver ----------------------------------------------------
extern "C" void kernel_launch(void* const* d_in, const int* in_sizes, int n_in,
                              void* d_out, int out_size)
{
    const float* q_embed = (const float*)d_in[0];
    const float* qa_embed= (const float*)d_in[1];
    const float* pos     = (const float*)d_in[2];
    const float* Wk  = (const float*)d_in[3];
    const float* bk  = (const float*)d_in[4];
    const float* Wv  = (const float*)d_in[5];
    const float* bv  = (const float*)d_in[6];
    const float* Wo  = (const float*)d_in[7];
    const float* bo  = (const float*)d_in[8];
    const float* ln1g= (const float*)d_in[9];
    const float* ln1b= (const float*)d_in[10];
    const float* W1  = (const float*)d_in[11];
    const float* b1  = (const float*)d_in[12];
    const float* W2  = (const float*)d_in[13];
    const float* b2  = (const float*)d_in[14];
    const float* ln2g= (const float*)d_in[15];
    const float* ln2b= (const float*)d_in[16];
    float* out = (float*)d_out;

    float *x, *y, *k, *vT, *t1, *t2, *ff, *sc;
    cudaGetSymbolAddress((void**)&x,  g_x);
    cudaGetSymbolAddress((void**)&y,  g_y);
    cudaGetSymbolAddress((void**)&k,  g_k);
    cudaGetSymbolAddress((void**)&vT, g_v);
    cudaGetSymbolAddress((void**)&t1, g_t1);
    cudaGetSymbolAddress((void**)&t2, g_t2);
    cudaGetSymbolAddress((void**)&ff, g_ff);
    cudaGetSymbolAddress((void**)&sc, g_sc);

    cudaFuncSetAttribute(gemm_mma, cudaFuncAttributeMaxDynamicSharedMemorySize,
                         DSMEM_BYTES);

    add_pos_kernel<<<(Bb*Ss*Dd)/256, 256>>>(q_embed, qa_embed, pos, x, y);

    const float inv_sqrt_dk = 0.08838834764831845f;  // 1/sqrt(128)

    for (int l = 0; l < Ll; l++) {
        const float* Wkl = Wk + (long)l*Dd*Dd;  const float* bkl = bk + (long)l*Dd;
        const float* Wvl = Wv + (long)l*Dd*Dd;  const float* bvl = bv + (long)l*Dd;
        const float* Wol = Wo + (long)l*Dd*Dd;  const float* bol = bo + (long)l*Dd;
        const float* W1l = W1 + (long)l*FFf*Dd; const float* b1l = b1 + (long)l*FFf;
        const float* W2l = W2 + (long)l*Dd*FFf; const float* b2l = b2 + (long)l*Dd;

        dim3 gP (Dd/128,  (Bb*Ss)/128, 1);    // projections 8192x1024 (K=1024)
        dim3 gS (Ss/128,  Ss/128,  Bb*Hh);    // scores 1024x1024 (K=128) x64
        dim3 gA (1,       Ss/128,  Bb*Hh);    // attn@V 1024x128 (K=1024) x64
        dim3 gF1(FFf/128, (Bb*Ss)/128, 1);    // FF1 8192x4096 (K=1024)
        dim3 gF2(Dd/128,  (Bb*Ss)/128, 1);    // FF2 8192x1024 (K=4096)

        // K = x @ Wk^T + bk   (q == k)
        gemm_mma<<<gP, 256, DSMEM_BYTES>>>(x, Dd, Wkl, Dd, bkl, k, Dd, Dd, 1,
                                           0,0,0,0,0,0, 1.f, 0, 0);
        // vT[b,h,dk,s] = (y @ Wv^T + bv) transposed
        gemm_mma<<<gP, 256, DSMEM_BYTES>>>(y, Dd, Wvl, Dd, bvl, vT, Dd, Dd, 1,
                                           0,0,0,0,0,0, 1.f, 0, 1);
        // scores[b,h] = (K_bh @ K_bh^T) / sqrt(DK)
        gemm_mma<<<gS, 256, DSMEM_BYTES>>>(k, Dd, k, Dd, nullptr, sc, Ss, DKk, Hh,
                                           (long)Ss*Dd, DKk,
                                           (long)Ss*Dd, DKk,
                                           (long)Hh*Ss*Ss, (long)Ss*Ss,
                                           inv_sqrt_dk, 0, 0);
        // masked softmax (strict causal, row 0 zeroed)
        softmax_rows<<<Bb*Hh*Ss, 256>>>(sc);
        // t1[b,:,h,:] = attn[b,h] @ V_bh   (NT against vT)
        gemm_mma<<<gA, 256, DSMEM_BYTES>>>(sc, Ss, vT, Ss, nullptr, t1, Dd, Ss, Hh,
                                           (long)Hh*Ss*Ss, (long)Ss*Ss,
                                           (long)Hh*DKk*Ss, (long)DKk*Ss,
                                           (long)Ss*Dd, DKk,
                                           1.f, 0, 0);
        // t2 = t1 @ Wo^T + bo
        gemm_mma<<<gP, 256, DSMEM_BYTES>>>(t1, Dd, Wol, Dd, bol, t2, Dd, Dd, 1,
                                           0,0,0,0,0,0, 1.f, 0, 0);
        // x = LN(x + t2)
        ln_res<<<Bb*Ss, 256>>>(x, t2, ln1g + (long)l*Dd, ln1b + (long)l*Dd, x);
        // ff = relu(x @ W1^T + b1)
        gemm_mma<<<gF1, 256, DSMEM_BYTES>>>(x, Dd, W1l, Dd, b1l, ff, FFf, Dd, 1,
                                            0,0,0,0,0,0, 1.f, 1, 0);
        // t2 = ff @ W2^T + b2
        gemm_mma<<<gF2, 256, DSMEM_BYTES>>>(ff, FFf, W2l, FFf, b2l, t2, Dd, FFf, 1,
                                            0,0,0,0,0,0, 1.f, 0, 0);
        // x = LN(x + t2); final layer writes straight to d_out
        float* xout = (l == Ll - 1) ? out : x;
        ln_res<<<Bb*Ss, 256>>>(x, t2, ln2g + (long)l*Dd, ln2b + (long)l*Dd, xout);
    }
}

// round 4
// speedup vs baseline: 4.2137x; 1.6837x over previous
#include <cuda_runtime.h>
#include <cuda_fp16.h>
#include <math.h>
#include <stdint.h>

// Problem constants
#define Bb 8
#define Ss 1024
#define Dd 1024
#define Hh 8
#define DKk 128
#define FFf 4096
#define Ll 2

// ---------------- scratch (device globals; no allocation allowed) ----------
__device__ float  g_x [Bb*Ss*Dd];                 // fp32 activation (residual)
__device__ float  g_t2[Bb*Ss*Dd];                 // fp32 branch output
__device__ float  g_sc[(size_t)Bb*Hh*Ss*Ss];      // fp32 scores (256 MB)
__device__ __half g_xh [Bb*Ss*Dd];
__device__ __half g_yh [Bb*Ss*Dd];
__device__ __half g_kh [Bb*Ss*Dd];
__device__ __half g_kl [Bb*Ss*Dd];
__device__ __half g_vh [Bb*Ss*Dd];                // vT hi  [b,h,dk,s]
__device__ __half g_vl [Bb*Ss*Dd];                // vT lo
__device__ __half g_t1h[Bb*Ss*Dd];
__device__ __half g_ffh[Bb*Ss*FFf];
__device__ __half g_sch[(size_t)Bb*Hh*Ss*Ss];     // fp16 probs (128 MB)
// weight splits (reused per layer)
__device__ __half g_wkh[Dd*Dd], g_wkl[Dd*Dd];
__device__ __half g_wvh[Dd*Dd], g_wvl[Dd*Dd];
__device__ __half g_woh[Dd*Dd], g_wol[Dd*Dd];
__device__ __half g_w1h[FFf*Dd], g_w1l[FFf*Dd];
__device__ __half g_w2h[Dd*FFf], g_w2l[Dd*FFf];

// ======================= helpers ============================================
__device__ __forceinline__ uint32_t smem_u32(const void* p) {
    uint32_t a;
    asm("{ .reg .u64 t; cvta.to.shared.u64 t, %1; cvt.u32.u64 %0, t; }"
        : "=r"(a) : "l"(p));
    return a;
}

__device__ __forceinline__ void ldsm4(uint32_t* r, uint32_t addr) {
    asm volatile("ldmatrix.sync.aligned.m8n8.x4.shared.b16 {%0,%1,%2,%3}, [%4];"
        : "=r"(r[0]), "=r"(r[1]), "=r"(r[2]), "=r"(r[3]) : "r"(addr));
}

__device__ __forceinline__ void mma16816(float* c, const uint32_t* a,
                                         const uint32_t* b) {
    asm volatile(
        "mma.sync.aligned.m16n8k16.row.col.f32.f16.f16.f32 "
        "{%0,%1,%2,%3}, {%4,%5,%6,%7}, {%8,%9}, {%0,%1,%2,%3};"
        : "+f"(c[0]), "+f"(c[1]), "+f"(c[2]), "+f"(c[3])
        : "r"(a[0]), "r"(a[1]), "r"(a[2]), "r"(a[3]), "r"(b[0]), "r"(b[1]));
}

__device__ __forceinline__ void cp16(uint32_t dst, const void* src) {
    asm volatile("cp.async.cg.shared.global [%0], [%1], 16;"
        :: "r"(dst), "l"(src));
}
#define CP_COMMIT() asm volatile("cp.async.commit_group;" ::: "memory")
#define CP_WAIT(n)  asm volatile("cp.async.wait_group %0;" :: "n"(n) : "memory")

// ---------------- small elementwise kernels ---------------------------------
__global__ void add_pos_kernel(const float* __restrict__ q,
                               const float* __restrict__ qa,
                               const float* __restrict__ pe,
                               float* __restrict__ x,
                               __half* __restrict__ xh,
                               __half* __restrict__ yh)
{
    int idx = blockIdx.x * 256 + threadIdx.x;
    int sd  = idx & (Ss*Dd - 1);
    float p = pe[sd];
    float xv = q[idx] + p;
    x[idx]  = xv;
    xh[idx] = __float2half(xv);
    yh[idx] = __float2half(qa[idx] + p);
}

__global__ void wsplit(const float* __restrict__ w,
                       __half* __restrict__ h, __half* __restrict__ l, int n)
{
    int i = blockIdx.x * 256 + threadIdx.x;
    if (i < n) {
        float v = w[i];
        __half hh = __float2half(v);
        h[i] = hh;
        l[i] = __float2half(v - __half2float(hh));
    }
}

// ============ fp16 2-term GEMM: C = alpha * A * (Bh+Bl)^T (+bias)(+relu) ====
// A (fp16, rounded side): [M,K] row-major. Bh/Bl (exact pair): [N,K] row-major.
// CTA tile 128x128, 4 warps of 64x64, K staged 32 wide, cp.async double buffer.
// outMode: 0=fp32 Cf; 1=fp16 Ch; 2=fp16 Ch+Cl pair; 3=pair + vT scatter.
// causal: skip blocks with n0 > m0.  klim: clamp K loop to m0+128 (attn@V).
#define ROWB 80
#define TILEB (128 * ROWB)          // 10240
#define STAGEB (3 * TILEB)          // 30720
#define DSMEM_BYTES (2 * STAGEB)    // 61440

__device__ __forceinline__ void load_stage(
    int tid, uint32_t base,
    const __half* A, int lda, const __half* Bh, const __half* Bl, int ldb,
    int m0, int n0, int k0)
{
#pragma unroll
    for (int j = 0; j < 4; j++) {
        int c = tid + j * 128;              // 0..511
        int row = c >> 2, c4 = c & 3;
        uint32_t off = (uint32_t)(row * ROWB + c4 * 16);
        cp16(base + off,             A  + (long)(m0 + row) * lda + k0 + c4 * 8);
        cp16(base + TILEB + off,     Bh + (long)(n0 + row) * ldb + k0 + c4 * 8);
        cp16(base + 2 * TILEB + off, Bl + (long)(n0 + row) * ldb + k0 + c4 * 8);
    }
}

__global__ void __launch_bounds__(128, 2)
gemm_h(const __half* __restrict__ A, int lda,
       const __half* __restrict__ Bh, const __half* __restrict__ Bl, int ldb,
       const float* __restrict__ bias,
       float* __restrict__ Cf, __half* __restrict__ Ch, __half* __restrict__ Cl,
       int ldc, int K, int bdiv,
       long sA0, long sA1, long sB0, long sB1, long sC0, long sC1,
       float alpha, int relu, int outMode, int causal, int klim)
{
    extern __shared__ char dsm[];
    const int m0 = blockIdx.y * 128, n0 = blockIdx.x * 128;
    if (causal && n0 > m0) return;      // fully-masked score block

    uint32_t sb = smem_u32(dsm);

    int z  = blockIdx.z;
    int zb = z / bdiv, zh = z - zb * bdiv;
    A  += zb * sA0 + zh * sA1;
    Bh += zb * sB0 + zh * sB1;
    Bl += zb * sB0 + zh * sB1;
    if (Cf) Cf += zb * sC0 + zh * sC1;
    if (Ch && outMode != 3) Ch += zb * sC0 + zh * sC1;
    if (Cl && outMode == 2) Cl += zb * sC0 + zh * sC1;

    const int tid  = threadIdx.x;
    const int lane = tid & 31, wid = tid >> 5;
    const int mW = (wid >> 1) * 64, nW = (wid & 1) * 64;

    const uint32_t aRowOff = (uint32_t)((mW + (lane & 15)) * ROWB + (lane >> 4) * 16);
    const uint32_t bRowOff = (uint32_t)((nW + (lane & 7) + ((lane >> 4) * 8)) * ROWB
                                        + ((lane >> 3) & 1) * 16);

    int nst = K >> 5;
    if (klim) { int lim = (m0 + 128) >> 5; nst = nst < lim ? nst : lim; }

    float acc[4][8][4] = {};

    load_stage(tid, sb, A, lda, Bh, Bl, ldb, m0, n0, 0);
    CP_COMMIT();

    for (int s = 0; s < nst; s++) {
        uint32_t cur = sb + (uint32_t)(s & 1) * STAGEB;
        if (s + 1 < nst) {
            load_stage(tid, sb + (uint32_t)((s + 1) & 1) * STAGEB,
                       A, lda, Bh, Bl, ldb, m0, n0, (s + 1) * 32);
            CP_COMMIT();
            CP_WAIT(1);
        } else {
            CP_WAIT(0);
        }
        __syncthreads();

#pragma unroll
        for (int kk = 0; kk < 2; kk++) {
            const uint32_t kb = kk * 32;
            uint32_t a[4][4], bh[4][4], bl[4][4];
#pragma unroll
            for (int mt = 0; mt < 4; mt++)
                ldsm4(a[mt], cur + aRowOff + mt * (16 * ROWB) + kb);
#pragma unroll
            for (int nh = 0; nh < 4; nh++)
                ldsm4(bh[nh], cur + TILEB + bRowOff + nh * (16 * ROWB) + kb);
#pragma unroll
            for (int nh = 0; nh < 4; nh++)
                ldsm4(bl[nh], cur + 2 * TILEB + bRowOff + nh * (16 * ROWB) + kb);
#pragma unroll
            for (int nh = 0; nh < 4; nh++)
#pragma unroll
                for (int hf = 0; hf < 2; hf++)
#pragma unroll
                    for (int mt = 0; mt < 4; mt++) {
                        mma16816(acc[mt][nh*2+hf], a[mt], bh[nh] + 2*hf);
                        mma16816(acc[mt][nh*2+hf], a[mt], bl[nh] + 2*hf);
                    }
        }
        __syncthreads();
    }

    // ---- epilogue ----
    const int rIn = lane >> 2, cIn = (lane & 3) * 2;
#pragma unroll
    for (int mt = 0; mt < 4; mt++) {
#pragma unroll
        for (int nt = 0; nt < 8; nt++) {
            float* a4 = acc[mt][nt];
            int col = n0 + nW + nt*8 + cIn;
            long r0 = (long)m0 + mW + mt*16 + rIn;
            long r1 = r0 + 8;
            float v0 = a4[0]*alpha, v1 = a4[1]*alpha;
            float v2 = a4[2]*alpha, v3 = a4[3]*alpha;
            if (bias) {
                float b0_ = bias[col], b1_ = bias[col+1];
                v0 += b0_; v1 += b1_; v2 += b0_; v3 += b1_;
            }
            if (relu) {
                v0 = fmaxf(v0,0.f); v1 = fmaxf(v1,0.f);
                v2 = fmaxf(v2,0.f); v3 = fmaxf(v3,0.f);
            }
            if (outMode == 0) {
                *(float2*)(Cf + r0*ldc + col) = make_float2(v0, v1);
                *(float2*)(Cf + r1*ldc + col) = make_float2(v2, v3);
            } else if (outMode == 1) {
                *(__half2*)(Ch + r0*ldc + col) = __floats2half2_rn(v0, v1);
                *(__half2*)(Ch + r1*ldc + col) = __floats2half2_rn(v2, v3);
            } else if (outMode == 2) {
                __half h0 = __float2half(v0), h1 = __float2half(v1);
                __half h2 = __float2half(v2), h3 = __float2half(v3);
                __half2 hi0; hi0.x = h0; hi0.y = h1;
                __half2 hi1; hi1.x = h2; hi1.y = h3;
                *(__half2*)(Ch + r0*ldc + col) = hi0;
                *(__half2*)(Ch + r1*ldc + col) = hi1;
                __half2 lo0; lo0.x = __float2half(v0 - __half2float(h0));
                lo0.y = __float2half(v1 - __half2float(h1));
                __half2 lo1; lo1.x = __float2half(v2 - __half2float(h2));
                lo1.y = __float2half(v3 - __half2float(h3));
                *(__half2*)(Cl + r0*ldc + col) = lo0;
                *(__half2*)(Cl + r1*ldc + col) = lo1;
            } else { // 3: vT scatter, pair
                int b0i = (int)(r0 >> 10), s0 = (int)(r0 & 1023);
                int b1i = (int)(r1 >> 10), s1 = (int)(r1 & 1023);
                int h = col >> 7, dk = col & 127;
                long i00 = ((long)((b0i*Hh + h)*DKk + dk)     << 10) + s0;
                long i01 = ((long)((b0i*Hh + h)*DKk + dk + 1) << 10) + s0;
                long i10 = ((long)((b1i*Hh + h)*DKk + dk)     << 10) + s1;
                long i11 = ((long)((b1i*Hh + h)*DKk + dk + 1) << 10) + s1;
                __half h0 = __float2half(v0), h1 = __float2half(v1);
                __half h2 = __float2half(v2), h3 = __float2half(v3);
                Ch[i00] = h0; Ch[i01] = h1; Ch[i10] = h2; Ch[i11] = h3;
                Cl[i00] = __float2half(v0 - __half2float(h0));
                Cl[i01] = __float2half(v1 - __half2float(h1));
                Cl[i10] = __float2half(v2 - __half2float(h2));
                Cl[i11] = __float2half(v3 - __half2float(h3));
            }
        }
    }
}

// ---------------- causal masked softmax: fp32 in, fp16 out ------------------
__global__ void softmax_rows(const float* __restrict__ sc,
                             __half* __restrict__ sch)
{
    __shared__ float red[256];
    long row = blockIdx.x;
    int  i   = (int)(row & (Ss - 1));
    const float* p = sc + row * (long)Ss;
    __half* o = sch + row * (long)Ss;
    int tid  = threadIdx.x;

    if (i == 0) {
        for (int j = tid; j < Ss; j += 256) o[j] = __float2half(0.f);
        return;
    }

    float v[4];
    float mx = -3.4e38f;
#pragma unroll
    for (int q = 0; q < 4; q++) {
        int j = tid + q * 256;
        v[q] = (j < i) ? p[j] : -3.4e38f;
        mx = fmaxf(mx, v[q]);
    }
    red[tid] = mx; __syncthreads();
    for (int off = 128; off > 0; off >>= 1) {
        if (tid < off) red[tid] = fmaxf(red[tid], red[tid + off]);
        __syncthreads();
    }
    mx = red[0]; __syncthreads();

    float e[4], s = 0.f;
#pragma unroll
    for (int q = 0; q < 4; q++) {
        int j = tid + q * 256;
        e[q] = (j < i) ? expf(v[q] - mx) : 0.f;
        s += e[q];
    }
    red[tid] = s; __syncthreads();
    for (int off = 128; off > 0; off >>= 1) {
        if (tid < off) red[tid] += red[tid + off];
        __syncthreads();
    }
    float inv = 1.f / red[0];

#pragma unroll
    for (int q = 0; q < 4; q++) {
        int j = tid + q * 256;
        o[j] = __float2half(e[q] * inv);
    }
}

// ---------------- residual add + LayerNorm (fp32 out + optional fp16) -------
__global__ void ln_res(const float* __restrict__ x, const float* __restrict__ t,
                       const float* __restrict__ g, const float* __restrict__ b,
                       float* __restrict__ out, __half* __restrict__ outh)
{
    __shared__ float red[256];
    long row = blockIdx.x;
    int tid = threadIdx.x;
    const float* xp = x + row * Dd;
    const float* tp = t + row * Dd;

    float v[4];
    float s = 0.f;
#pragma unroll
    for (int q = 0; q < 4; q++) {
        int c = tid + q * 256;
        v[q] = xp[c] + tp[c];
        s += v[q];
    }
    red[tid] = s; __syncthreads();
    for (int off = 128; off > 0; off >>= 1) {
        if (tid < off) red[tid] += red[tid + off];
        __syncthreads();
    }
    float mean = red[0] * (1.f / Dd);
    __syncthreads();

    float s2 = 0.f;
#pragma unroll
    for (int q = 0; q < 4; q++) {
        float d = v[q] - mean;
        s2 += d * d;
    }
    red[tid] = s2; __syncthreads();
    for (int off = 128; off > 0; off >>= 1) {
        if (tid < off) red[tid] += red[tid + off];
        __syncthreads();
    }
    float inv = rsqrtf(red[0] * (1.f / Dd) + 1e-5f);

#pragma unroll
    for (int q = 0; q < 4; q++) {
        int c = tid + q * 256;
        float val = (v[q] - mean) * inv * g[c] + b[c];
        out[row * Dd + c] = val;
        if (outh) outh[row * Dd + c] = __float2half(val);
    }
}

// ---------------- driver ----------------------------------------------------
extern "C" void kernel_launch(void* const* d_in, const int* in_sizes, int n_in,
                              void* d_out, int out_size)
{
    const float* q_embed = (const float*)d_in[0];
    const float* qa_embed= (const float*)d_in[1];
    const float* pos     = (const float*)d_in[2];
    const float* Wk  = (const float*)d_in[3];
    const float* bk  = (const float*)d_in[4];
    const float* Wv  = (const float*)d_in[5];
    const float* bv  = (const float*)d_in[6];
    const float* Wo  = (const float*)d_in[7];
    const float* bo  = (const float*)d_in[8];
    const float* ln1g= (const float*)d_in[9];
    const float* ln1b= (const float*)d_in[10];
    const float* W1  = (const float*)d_in[11];
    const float* b1  = (const float*)d_in[12];
    const float* W2  = (const float*)d_in[13];
    const float* b2  = (const float*)d_in[14];
    const float* ln2g= (const float*)d_in[15];
    const float* ln2b= (const float*)d_in[16];
    float* out = (float*)d_out;

    float *x, *t2, *sc;
    __half *xh, *yh, *kh, *kl, *vh, *vl, *t1h, *ffh, *sch;
    __half *wkh, *wkl, *wvh, *wvl, *woh, *wol, *w1h, *w1l, *w2h, *w2l;
    cudaGetSymbolAddress((void**)&x,   g_x);
    cudaGetSymbolAddress((void**)&t2,  g_t2);
    cudaGetSymbolAddress((void**)&sc,  g_sc);
    cudaGetSymbolAddress((void**)&xh,  g_xh);
    cudaGetSymbolAddress((void**)&yh,  g_yh);
    cudaGetSymbolAddress((void**)&kh,  g_kh);
    cudaGetSymbolAddress((void**)&kl,  g_kl);
    cudaGetSymbolAddress((void**)&vh,  g_vh);
    cudaGetSymbolAddress((void**)&vl,  g_vl);
    cudaGetSymbolAddress((void**)&t1h, g_t1h);
    cudaGetSymbolAddress((void**)&ffh, g_ffh);
    cudaGetSymbolAddress((void**)&sch, g_sch);
    cudaGetSymbolAddress((void**)&wkh, g_wkh);  cudaGetSymbolAddress((void**)&wkl, g_wkl);
    cudaGetSymbolAddress((void**)&wvh, g_wvh);  cudaGetSymbolAddress((void**)&wvl, g_wvl);
    cudaGetSymbolAddress((void**)&woh, g_woh);  cudaGetSymbolAddress((void**)&wol, g_wol);
    cudaGetSymbolAddress((void**)&w1h, g_w1h);  cudaGetSymbolAddress((void**)&w1l, g_w1l);
    cudaGetSymbolAddress((void**)&w2h, g_w2h);  cudaGetSymbolAddress((void**)&w2l, g_w2l);

    cudaFuncSetAttribute(gemm_h, cudaFuncAttributeMaxDynamicSharedMemorySize,
                         DSMEM_BYTES);

    add_pos_kernel<<<(Bb*Ss*Dd)/256, 256>>>(q_embed, qa_embed, pos, x, xh, yh);

    const float inv_sqrt_dk = 0.08838834764831845f;  // 1/sqrt(128)

    for (int l = 0; l < Ll; l++) {
        const float* bkl_ = bk + (long)l*Dd;
        const float* bvl_ = bv + (long)l*Dd;
        const float* bol_ = bo + (long)l*Dd;
        const float* b1l_ = b1 + (long)l*FFf;
        const float* b2l_ = b2 + (long)l*Dd;

        // split this layer's weights into fp16 hi/lo pairs
        wsplit<<<(Dd*Dd)/256, 256>>>(Wk + (long)l*Dd*Dd, wkh, wkl, Dd*Dd);
        wsplit<<<(Dd*Dd)/256, 256>>>(Wv + (long)l*Dd*Dd, wvh, wvl, Dd*Dd);
        wsplit<<<(Dd*Dd)/256, 256>>>(Wo + (long)l*Dd*Dd, woh, wol, Dd*Dd);
        wsplit<<<(FFf*Dd)/256, 256>>>(W1 + (long)l*FFf*Dd, w1h, w1l, FFf*Dd);
        wsplit<<<(Dd*FFf)/256, 256>>>(W2 + (long)l*Dd*FFf, w2h, w2l, Dd*FFf);

        dim3 gP (Dd/128,  (Bb*Ss)/128, 1);
        dim3 gS (Ss/128,  Ss/128,  Bb*Hh);
        dim3 gA (1,       Ss/128,  Bb*Hh);
        dim3 gF1(FFf/128, (Bb*Ss)/128, 1);
        dim3 gF2(Dd/128,  (Bb*Ss)/128, 1);

        // K = x @ Wk^T + bk  -> fp16 pair (k is the exact side of scores GEMM)
        gemm_h<<<gP, 128, DSMEM_BYTES>>>(xh, Dd, wkh, wkl, Dd, bkl_,
            nullptr, kh, kl, Dd, Dd, 1, 0,0,0,0,0,0, 1.f, 0, 2, 0, 0);
        // vT = (y @ Wv^T + bv)^T scatter -> fp16 pair
        gemm_h<<<gP, 128, DSMEM_BYTES>>>(yh, Dd, wvh, wvl, Dd, bvl_,
            nullptr, vh, vl, Dd, Dd, 1, 0,0,0,0,0,0, 1.f, 0, 3, 0, 0);
        // scores[b,h] = kh_i . (kh+kl)_j / sqrt(DK); skip above-diagonal blocks
        gemm_h<<<gS, 128, DSMEM_BYTES>>>(kh, Dd, kh, kl, Dd, nullptr,
            sc, nullptr, nullptr, Ss, DKk, Hh,
            (long)Ss*Dd, 128, (long)Ss*Dd, 128,
            (long)Hh*Ss*Ss, (long)Ss*Ss,
            inv_sqrt_dk, 0, 0, 1, 0);
        // masked softmax -> fp16 probs
        softmax_rows<<<Bb*Hh*Ss, 256>>>(sc, sch);
        // t1 = probs @ V  (B = vT pair, K clamped causally) -> fp16 hi
        gemm_h<<<gA, 128, DSMEM_BYTES>>>(sch, Ss, vh, vl, Ss, nullptr,
            nullptr, t1h, nullptr, Dd, Ss, Hh,
            (long)Hh*Ss*Ss, (long)Ss*Ss,
            (long)Hh*DKk*Ss, (long)DKk*Ss,
            (long)Ss*Dd, 128,
            1.f, 0, 1, 0, 1);
        // t2 = t1 @ Wo^T + bo -> fp32
        gemm_h<<<gP, 128, DSMEM_BYTES>>>(t1h, Dd, woh, wol, Dd, bol_,
            t2, nullptr, nullptr, Dd, Dd, 1, 0,0,0,0,0,0, 1.f, 0, 0, 0, 0);
        // x = LN(x + t2) -> fp32 + fp16
        ln_res<<<Bb*Ss, 256>>>(x, t2, ln1g + (long)l*Dd, ln1b + (long)l*Dd, x, xh);
        // ff = relu(x @ W1^T + b1) -> fp16 hi
        gemm_h<<<gF1, 128, DSMEM_BYTES>>>(xh, Dd, w1h, w1l, Dd, b1l_,
            nullptr, ffh, nullptr, FFf, Dd, 1, 0,0,0,0,0,0, 1.f, 1, 1, 0, 0);
        // t2 = ff @ W2^T + b2 -> fp32
        gemm_h<<<gF2, 128, DSMEM_BYTES>>>(ffh, FFf, w2h, w2l, FFf, b2l_,
            t2, nullptr, nullptr, Dd, FFf, 1, 0,0,0,0,0,0, 1.f, 0, 0, 0, 0);
        // x = LN(x + t2); final layer -> d_out (fp32 only)
        float* xout = (l == Ll - 1) ? out : x;
        __half* xhout = (l == Ll - 1) ? nullptr : xh;
        ln_res<<<Bb*Ss, 256>>>(x, t2, ln2g + (long)l*Dd, ln2b + (long)l*Dd,
                               xout, xhout);
    }
}

// round 5
// speedup vs baseline: 6.8606x; 1.6282x over previous
#include <cuda_runtime.h>
#include <cuda_fp16.h>
#include <math.h>
#include <stdint.h>

// Problem constants
#define Bb 8
#define Ss 1024
#define Dd 1024
#define Hh 8
#define DKk 128
#define FFf 4096
#define Ll 2

// ---------------- scratch (device globals; no allocation allowed) ----------
__device__ float  g_x [Bb*Ss*Dd];                 // fp32 activation (residual)
__device__ float  g_t2[Bb*Ss*Dd];                 // fp32 branch output
__device__ float  g_sc[(size_t)Bb*Hh*Ss*Ss];      // fp32 scores (256 MB)
__device__ __half g_xh [Bb*Ss*Dd];
__device__ __half g_yh [Bb*Ss*Dd];
__device__ __half g_kh [Bb*Ss*Dd];
__device__ __half g_vh [Bb*Ss*Dd];                // vT [b,h,dk,s]
__device__ __half g_t1h[Bb*Ss*Dd];
__device__ __half g_ffh[Bb*Ss*FFf];
__device__ __half g_sch[(size_t)Bb*Hh*Ss*Ss];     // fp16 probs (128 MB)
// fp16 weights (converted per layer)
__device__ __half g_wk[Dd*Dd];
__device__ __half g_wv[Dd*Dd];
__device__ __half g_wo[Dd*Dd];
__device__ __half g_w1[FFf*Dd];
__device__ __half g_w2[Dd*FFf];

// ======================= helpers ============================================
__device__ __forceinline__ uint32_t smem_u32(const void* p) {
    uint32_t a;
    asm("{ .reg .u64 t; cvta.to.shared.u64 t, %1; cvt.u32.u64 %0, t; }"
        : "=r"(a) : "l"(p));
    return a;
}

__device__ __forceinline__ void ldsm4(uint32_t* r, uint32_t addr) {
    asm volatile("ldmatrix.sync.aligned.m8n8.x4.shared.b16 {%0,%1,%2,%3}, [%4];"
        : "=r"(r[0]), "=r"(r[1]), "=r"(r[2]), "=r"(r[3]) : "r"(addr));
}

__device__ __forceinline__ void mma16816(float* c, const uint32_t* a,
                                         const uint32_t* b) {
    asm volatile(
        "mma.sync.aligned.m16n8k16.row.col.f32.f16.f16.f32 "
        "{%0,%1,%2,%3}, {%4,%5,%6,%7}, {%8,%9}, {%0,%1,%2,%3};"
        : "+f"(c[0]), "+f"(c[1]), "+f"(c[2]), "+f"(c[3])
        : "r"(a[0]), "r"(a[1]), "r"(a[2]), "r"(a[3]), "r"(b[0]), "r"(b[1]));
}

__device__ __forceinline__ void cp16(uint32_t dst, const void* src) {
    asm volatile("cp.async.cg.shared.global [%0], [%1], 16;"
        :: "r"(dst), "l"(src));
}
#define CP_COMMIT() asm volatile("cp.async.commit_group;" ::: "memory")
#define CP_WAIT(n)  asm volatile("cp.async.wait_group %0;" :: "n"(n) : "memory")

// ---------------- small elementwise kernels ---------------------------------
__global__ void add_pos_kernel(const float* __restrict__ q,
                               const float* __restrict__ qa,
                               const float* __restrict__ pe,
                               float* __restrict__ x,
                               __half* __restrict__ xh,
                               __half* __restrict__ yh)
{
    int idx = blockIdx.x * 256 + threadIdx.x;
    int sd  = idx & (Ss*Dd - 1);
    float p = pe[sd];
    float xv = q[idx] + p;
    x[idx]  = xv;
    xh[idx] = __float2half(xv);
    yh[idx] = __float2half(qa[idx] + p);
}

__global__ void wconv(const float* __restrict__ w,
                      __half* __restrict__ h, int n)
{
    int i = blockIdx.x * 256 + threadIdx.x;
    if (i < n) h[i] = __float2half(w[i]);
}

// ============ fp16 GEMM: C = alpha * A * B^T (+bias)(+relu) =================
// A: [M,K] fp16 row-major. B: [N,K] fp16 row-major. fp32 accumulate.
// CTA tile 128x128, 4 warps of 64x64, K staged 32 wide, 3-stage cp.async ring.
// outMode: 0 = fp32 Cf; 1 = fp16 Ch; 3 = fp16 Ch with vT scatter.
// causal: skip blocks with n0 > m0.  klim: clamp K loop to m0+128 (attn@V).
#define ROWB 80
#define TILEB (128 * ROWB)          // 10240
#define STAGEB (2 * TILEB)          // 20480 (A tile + B tile)
#define NSTAGE 3
#define DSMEM_BYTES (NSTAGE * STAGEB)   // 61440

__device__ __forceinline__ void load_stage(
    int tid, uint32_t base,
    const __half* A, int lda, const __half* B, int ldb,
    int m0, int n0, int k0)
{
#pragma unroll
    for (int j = 0; j < 4; j++) {
        int c = tid + j * 128;              // 0..511
        int row = c >> 2, c4 = c & 3;
        uint32_t off = (uint32_t)(row * ROWB + c4 * 16);
        cp16(base + off,         A + (long)(m0 + row) * lda + k0 + c4 * 8);
        cp16(base + TILEB + off, B + (long)(n0 + row) * ldb + k0 + c4 * 8);
    }
}

__global__ void __launch_bounds__(128, 2)
gemm_h(const __half* __restrict__ A, int lda,
       const __half* __restrict__ B, int ldb,
       const float* __restrict__ bias,
       float* __restrict__ Cf, __half* __restrict__ Ch,
       int ldc, int K, int bdiv,
       long sA0, long sA1, long sB0, long sB1, long sC0, long sC1,
       float alpha, int relu, int outMode, int causal, int klim)
{
    extern __shared__ char dsm[];
    const int m0 = blockIdx.y * 128, n0 = blockIdx.x * 128;
    if (causal && n0 > m0) return;      // fully-masked score block

    uint32_t sb = smem_u32(dsm);

    int z  = blockIdx.z;
    int zb = z / bdiv, zh = z - zb * bdiv;
    A += zb * sA0 + zh * sA1;
    B += zb * sB0 + zh * sB1;
    if (Cf) Cf += zb * sC0 + zh * sC1;
    if (Ch && outMode != 3) Ch += zb * sC0 + zh * sC1;

    const int tid  = threadIdx.x;
    const int lane = tid & 31, wid = tid >> 5;
    const int mW = (wid >> 1) * 64, nW = (wid & 1) * 64;

    const uint32_t aRowOff = (uint32_t)((mW + (lane & 15)) * ROWB + (lane >> 4) * 16);
    const uint32_t bRowOff = (uint32_t)((nW + (lane & 7) + ((lane >> 4) * 8)) * ROWB
                                        + ((lane >> 3) & 1) * 16);

    int nst = K >> 5;
    if (klim) { int lim = (m0 + 128) >> 5; nst = nst < lim ? nst : lim; }

    float acc[4][8][4] = {};

    // 3-stage pipeline prologue
    load_stage(tid, sb, A, lda, B, ldb, m0, n0, 0);
    CP_COMMIT();
    if (nst > 1) load_stage(tid, sb + STAGEB, A, lda, B, ldb, m0, n0, 32);
    CP_COMMIT();

    int slot = 0;
    for (int s = 0; s < nst; s++) {
        CP_WAIT(1);
        __syncthreads();
        uint32_t cur = sb + (uint32_t)slot * STAGEB;

#pragma unroll
        for (int kk = 0; kk < 2; kk++) {
            const uint32_t kb = kk * 32;
            uint32_t a[4][4], b[4][4];
#pragma unroll
            for (int mt = 0; mt < 4; mt++)
                ldsm4(a[mt], cur + aRowOff + mt * (16 * ROWB) + kb);
#pragma unroll
            for (int nh = 0; nh < 4; nh++)
                ldsm4(b[nh], cur + TILEB + bRowOff + nh * (16 * ROWB) + kb);
#pragma unroll
            for (int nh = 0; nh < 4; nh++)
#pragma unroll
                for (int hf = 0; hf < 2; hf++)
#pragma unroll
                    for (int mt = 0; mt < 4; mt++)
                        mma16816(acc[mt][nh*2+hf], a[mt], b[nh] + 2*hf);
        }
        __syncthreads();
        if (s + 2 < nst) {
            int nslot = slot + 2; if (nslot >= NSTAGE) nslot -= NSTAGE;
            load_stage(tid, sb + (uint32_t)nslot * STAGEB,
                       A, lda, B, ldb, m0, n0, (s + 2) * 32);
        }
        CP_COMMIT();
        slot++; if (slot == NSTAGE) slot = 0;
    }

    // ---- epilogue ----
    const int rIn = lane >> 2, cIn = (lane & 3) * 2;
#pragma unroll
    for (int mt = 0; mt < 4; mt++) {
#pragma unroll
        for (int nt = 0; nt < 8; nt++) {
            float* a4 = acc[mt][nt];
            int col = n0 + nW + nt*8 + cIn;
            long r0 = (long)m0 + mW + mt*16 + rIn;
            long r1 = r0 + 8;
            float v0 = a4[0]*alpha, v1 = a4[1]*alpha;
            float v2 = a4[2]*alpha, v3 = a4[3]*alpha;
            if (bias) {
                float b0_ = bias[col], b1_ = bias[col+1];
                v0 += b0_; v1 += b1_; v2 += b0_; v3 += b1_;
            }
            if (relu) {
                v0 = fmaxf(v0,0.f); v1 = fmaxf(v1,0.f);
                v2 = fmaxf(v2,0.f); v3 = fmaxf(v3,0.f);
            }
            if (outMode == 0) {
                *(float2*)(Cf + r0*ldc + col) = make_float2(v0, v1);
                *(float2*)(Cf + r1*ldc + col) = make_float2(v2, v3);
            } else if (outMode == 1) {
                *(__half2*)(Ch + r0*ldc + col) = __floats2half2_rn(v0, v1);
                *(__half2*)(Ch + r1*ldc + col) = __floats2half2_rn(v2, v3);
            } else { // 3: vT scatter
                int b0i = (int)(r0 >> 10), s0 = (int)(r0 & 1023);
                int b1i = (int)(r1 >> 10), s1 = (int)(r1 & 1023);
                int h = col >> 7, dk = col & 127;
                long i00 = ((long)((b0i*Hh + h)*DKk + dk)     << 10) + s0;
                long i01 = ((long)((b0i*Hh + h)*DKk + dk + 1) << 10) + s0;
                long i10 = ((long)((b1i*Hh + h)*DKk + dk)     << 10) + s1;
                long i11 = ((long)((b1i*Hh + h)*DKk + dk + 1) << 10) + s1;
                Ch[i00] = __float2half(v0);
                Ch[i01] = __float2half(v1);
                Ch[i10] = __float2half(v2);
                Ch[i11] = __float2half(v3);
            }
        }
    }
}

// ---------------- causal masked softmax: fp32 in, fp16 out ------------------
__global__ void softmax_rows(const float* __restrict__ sc,
                             __half* __restrict__ sch)
{
    __shared__ float red[256];
    long row = blockIdx.x;
    int  i   = (int)(row & (Ss - 1));
    const float* p = sc + row * (long)Ss;
    __half* o = sch + row * (long)Ss;
    int tid  = threadIdx.x;

    if (i == 0) {
        for (int j = tid; j < Ss; j += 256) o[j] = __float2half(0.f);
        return;
    }

    float v[4];
    float mx = -3.4e38f;
#pragma unroll
    for (int q = 0; q < 4; q++) {
        int j = tid + q * 256;
        v[q] = (j < i) ? p[j] : -3.4e38f;
        mx = fmaxf(mx, v[q]);
    }
    red[tid] = mx; __syncthreads();
    for (int off = 128; off > 0; off >>= 1) {
        if (tid < off) red[tid] = fmaxf(red[tid], red[tid + off]);
        __syncthreads();
    }
    mx = red[0]; __syncthreads();

    float e[4], s = 0.f;
#pragma unroll
    for (int q = 0; q < 4; q++) {
        int j = tid + q * 256;
        e[q] = (j < i) ? expf(v[q] - mx) : 0.f;
        s += e[q];
    }
    red[tid] = s; __syncthreads();
    for (int off = 128; off > 0; off >>= 1) {
        if (tid < off) red[tid] += red[tid + off];
        __syncthreads();
    }
    float inv = 1.f / red[0];

#pragma unroll
    for (int q = 0; q < 4; q++) {
        int j = tid + q * 256;
        o[j] = __float2half(e[q] * inv);
    }
}

// ---------------- residual add + LayerNorm (fp32 out + optional fp16) -------
__global__ void ln_res(const float* __restrict__ x, const float* __restrict__ t,
                       const float* __restrict__ g, const float* __restrict__ b,
                       float* __restrict__ out, __half* __restrict__ outh)
{
    __shared__ float red[256];
    long row = blockIdx.x;
    int tid = threadIdx.x;
    const float* xp = x + row * Dd;
    const float* tp = t + row * Dd;

    float v[4];
    float s = 0.f;
#pragma unroll
    for (int q = 0; q < 4; q++) {
        int c = tid + q * 256;
        v[q] = xp[c] + tp[c];
        s += v[q];
    }
    red[tid] = s; __syncthreads();
    for (int off = 128; off > 0; off >>= 1) {
        if (tid < off) red[tid] += red[tid + off];
        __syncthreads();
    }
    float mean = red[0] * (1.f / Dd);
    __syncthreads();

    float s2 = 0.f;
#pragma unroll
    for (int q = 0; q < 4; q++) {
        float d = v[q] - mean;
        s2 += d * d;
    }
    red[tid] = s2; __syncthreads();
    for (int off = 128; off > 0; off >>= 1) {
        if (tid < off) red[tid] += red[tid + off];
        __syncthreads();
    }
    float inv = rsqrtf(red[0] * (1.f / Dd) + 1e-5f);

#pragma unroll
    for (int q = 0; q < 4; q++) {
        int c = tid + q * 256;
        float val = (v[q] - mean) * inv * g[c] + b[c];
        out[row * Dd + c] = val;
        if (outh) outh[row * Dd + c] = __float2half(val);
    }
}

// ---------------- driver ----------------------------------------------------
extern "C" void kernel_launch(void* const* d_in, const int* in_sizes, int n_in,
                              void* d_out, int out_size)
{
    const float* q_embed = (const float*)d_in[0];
    const float* qa_embed= (const float*)d_in[1];
    const float* pos     = (const float*)d_in[2];
    const float* Wk  = (const float*)d_in[3];
    const float* bk  = (const float*)d_in[4];
    const float* Wv  = (const float*)d_in[5];
    const float* bv  = (const float*)d_in[6];
    const float* Wo  = (const float*)d_in[7];
    const float* bo  = (const float*)d_in[8];
    const float* ln1g= (const float*)d_in[9];
    const float* ln1b= (const float*)d_in[10];
    const float* W1  = (const float*)d_in[11];
    const float* b1  = (const float*)d_in[12];
    const float* W2  = (const float*)d_in[13];
    const float* b2  = (const float*)d_in[14];
    const float* ln2g= (const float*)d_in[15];
    const float* ln2b= (const float*)d_in[16];
    float* out = (float*)d_out;

    float *x, *t2, *sc;
    __half *xh, *yh, *kh, *vh, *t1h, *ffh, *sch;
    __half *wk, *wv, *wo, *w1, *w2;
    cudaGetSymbolAddress((void**)&x,   g_x);
    cudaGetSymbolAddress((void**)&t2,  g_t2);
    cudaGetSymbolAddress((void**)&sc,  g_sc);
    cudaGetSymbolAddress((void**)&xh,  g_xh);
    cudaGetSymbolAddress((void**)&yh,  g_yh);
    cudaGetSymbolAddress((void**)&kh,  g_kh);
    cudaGetSymbolAddress((void**)&vh,  g_vh);
    cudaGetSymbolAddress((void**)&t1h, g_t1h);
    cudaGetSymbolAddress((void**)&ffh, g_ffh);
    cudaGetSymbolAddress((void**)&sch, g_sch);
    cudaGetSymbolAddress((void**)&wk,  g_wk);
    cudaGetSymbolAddress((void**)&wv,  g_wv);
    cudaGetSymbolAddress((void**)&wo,  g_wo);
    cudaGetSymbolAddress((void**)&w1,  g_w1);
    cudaGetSymbolAddress((void**)&w2,  g_w2);

    cudaFuncSetAttribute(gemm_h, cudaFuncAttributeMaxDynamicSharedMemorySize,
                         DSMEM_BYTES);

    add_pos_kernel<<<(Bb*Ss*Dd)/256, 256>>>(q_embed, qa_embed, pos, x, xh, yh);

    const float inv_sqrt_dk = 0.08838834764831845f;  // 1/sqrt(128)

    for (int l = 0; l < Ll; l++) {
        const float* bkl_ = bk + (long)l*Dd;
        const float* bvl_ = bv + (long)l*Dd;
        const float* bol_ = bo + (long)l*Dd;
        const float* b1l_ = b1 + (long)l*FFf;
        const float* b2l_ = b2 + (long)l*Dd;

        // convert this layer's weights to fp16
        wconv<<<(Dd*Dd)/256, 256>>>(Wk + (long)l*Dd*Dd, wk, Dd*Dd);
        wconv<<<(Dd*Dd)/256, 256>>>(Wv + (long)l*Dd*Dd, wv, Dd*Dd);
        wconv<<<(Dd*Dd)/256, 256>>>(Wo + (long)l*Dd*Dd, wo, Dd*Dd);
        wconv<<<(FFf*Dd)/256, 256>>>(W1 + (long)l*FFf*Dd, w1, FFf*Dd);
        wconv<<<(Dd*FFf)/256, 256>>>(W2 + (long)l*Dd*FFf, w2, Dd*FFf);

        dim3 gP (Dd/128,  (Bb*Ss)/128, 1);
        dim3 gS (Ss/128,  Ss/128,  Bb*Hh);
        dim3 gA (1,       Ss/128,  Bb*Hh);
        dim3 gF1(FFf/128, (Bb*Ss)/128, 1);
        dim3 gF2(Dd/128,  (Bb*Ss)/128, 1);

        // K = x @ Wk^T + bk  -> fp16
        gemm_h<<<gP, 128, DSMEM_BYTES>>>(xh, Dd, wk, Dd, bkl_,
            nullptr, kh, Dd, Dd, 1, 0,0,0,0,0,0, 1.f, 0, 1, 0, 0);
        // vT = (y @ Wv^T + bv)^T scatter -> fp16
        gemm_h<<<gP, 128, DSMEM_BYTES>>>(yh, Dd, wv, Dd, bvl_,
            nullptr, vh, Dd, Dd, 1, 0,0,0,0,0,0, 1.f, 0, 3, 0, 0);
        // scores[b,h] = k_i . k_j / sqrt(DK); skip above-diagonal blocks
        gemm_h<<<gS, 128, DSMEM_BYTES>>>(kh, Dd, kh, Dd, nullptr,
            sc, nullptr, Ss, DKk, Hh,
            (long)Ss*Dd, 128, (long)Ss*Dd, 128,
            (long)Hh*Ss*Ss, (long)Ss*Ss,
            inv_sqrt_dk, 0, 0, 1, 0);
        // masked softmax -> fp16 probs
        softmax_rows<<<Bb*Hh*Ss, 256>>>(sc, sch);
        // t1 = probs @ V  (B = vT, K clamped causally) -> fp16
        gemm_h<<<gA, 128, DSMEM_BYTES>>>(sch, Ss, vh, Ss, nullptr,
            nullptr, t1h, Dd, Ss, Hh,
            (long)Hh*Ss*Ss, (long)Ss*Ss,
            (long)Hh*DKk*Ss, (long)DKk*Ss,
            (long)Ss*Dd, 128,
            1.f, 0, 1, 0, 1);
        // t2 = t1 @ Wo^T + bo -> fp32
        gemm_h<<<gP, 128, DSMEM_BYTES>>>(t1h, Dd, wo, Dd, bol_,
            t2, nullptr, Dd, Dd, 1, 0,0,0,0,0,0, 1.f, 0, 0, 0, 0);
        // x = LN(x + t2) -> fp32 + fp16
        ln_res<<<Bb*Ss, 256>>>(x, t2, ln1g + (long)l*Dd, ln1b + (long)l*Dd, x, xh);
        // ff = relu(x @ W1^T + b1) -> fp16
        gemm_h<<<gF1, 128, DSMEM_BYTES>>>(xh, Dd, w1, Dd, b1l_,
            nullptr, ffh, FFf, Dd, 1, 0,0,0,0,0,0, 1.f, 1, 1, 0, 0);
        // t2 = ff @ W2^T + b2 -> fp32
        gemm_h<<<gF2, 128, DSMEM_BYTES>>>(ffh, FFf, w2, FFf, b2l_,
            t2, nullptr, Dd, FFf, 1, 0,0,0,0,0,0, 1.f, 0, 0, 0, 0);
        // x = LN(x + t2); final layer -> d_out (fp32 only)
        float* xout = (l == Ll - 1) ? out : x;
        __half* xhout = (l == Ll - 1) ? nullptr : xh;
        ln_res<<<Bb*Ss, 256>>>(x, t2, ln2g + (long)l*Dd, ln2b + (long)l*Dd,
                               xout, xhout);
    }
}

// round 6
// speedup vs baseline: 6.9043x; 1.0064x over previous
#include <cuda_runtime.h>
#include <cuda_fp16.h>
#include <math.h>
#include <stdint.h>

// Problem constants
#define Bb 8
#define Ss 1024
#define Dd 1024
#define Hh 8
#define DKk 128
#define FFf 4096
#define Ll 2

// ---------------- scratch (device globals; no allocation allowed) ----------
__device__ float  g_x [Bb*Ss*Dd];                 // fp32 activation (residual)
__device__ float  g_t2[Bb*Ss*Dd];                 // fp32 branch output
__device__ __half g_xh [Bb*Ss*Dd];
__device__ __half g_yh [Bb*Ss*Dd];
__device__ __half g_kh [Bb*Ss*Dd];
__device__ __half g_vh [Bb*Ss*Dd];                // vT [b,h,dk,s]
__device__ __half g_t1h[Bb*Ss*Dd];
__device__ __half g_ffh[Bb*Ss*FFf];
// fp16 weights (converted per layer)
__device__ __half g_wk[Dd*Dd];
__device__ __half g_wv[Dd*Dd];
__device__ __half g_wo[Dd*Dd];
__device__ __half g_w1[FFf*Dd];
__device__ __half g_w2[Dd*FFf];

// ======================= helpers ============================================
__device__ __forceinline__ uint32_t smem_u32(const void* p) {
    uint32_t a;
    asm("{ .reg .u64 t; cvta.to.shared.u64 t, %1; cvt.u32.u64 %0, t; }"
        : "=r"(a) : "l"(p));
    return a;
}

__device__ __forceinline__ void ldsm4(uint32_t* r, uint32_t addr) {
    asm volatile("ldmatrix.sync.aligned.m8n8.x4.shared.b16 {%0,%1,%2,%3}, [%4];"
        : "=r"(r[0]), "=r"(r[1]), "=r"(r[2]), "=r"(r[3]) : "r"(addr));
}

__device__ __forceinline__ void mma16816(float* c, const uint32_t* a,
                                         const uint32_t* b) {
    asm volatile(
        "mma.sync.aligned.m16n8k16.row.col.f32.f16.f16.f32 "
        "{%0,%1,%2,%3}, {%4,%5,%6,%7}, {%8,%9}, {%0,%1,%2,%3};"
        : "+f"(c[0]), "+f"(c[1]), "+f"(c[2]), "+f"(c[3])
        : "r"(a[0]), "r"(a[1]), "r"(a[2]), "r"(a[3]), "r"(b[0]), "r"(b[1]));
}

__device__ __forceinline__ void cp16(uint32_t dst, const void* src) {
    asm volatile("cp.async.cg.shared.global [%0], [%1], 16;"
        :: "r"(dst), "l"(src));
}
#define CP_COMMIT() asm volatile("cp.async.commit_group;" ::: "memory")
#define CP_WAIT(n)  asm volatile("cp.async.wait_group %0;" :: "n"(n) : "memory")

__device__ __forceinline__ uint32_t h2u(float a, float b) {
    __half2 h = __floats2half2_rn(a, b);
    return *(uint32_t*)&h;
}

// ---------------- small elementwise kernels ---------------------------------
__global__ void add_pos_kernel(const float* __restrict__ q,
                               const float* __restrict__ qa,
                               const float* __restrict__ pe,
                               float* __restrict__ x,
                               __half* __restrict__ xh,
                               __half* __restrict__ yh)
{
    int idx = blockIdx.x * 256 + threadIdx.x;
    int sd  = idx & (Ss*Dd - 1);
    float p = pe[sd];
    float xv = q[idx] + p;
    x[idx]  = xv;
    xh[idx] = __float2half(xv);
    yh[idx] = __float2half(qa[idx] + p);
}

__global__ void wconv(const float* __restrict__ w,
                      __half* __restrict__ h, int n)
{
    int i = blockIdx.x * 256 + threadIdx.x;
    if (i < n) h[i] = __float2half(w[i]);
}

// ============ fp16 GEMM: C = A * B^T (+bias)(+relu) =========================
// A: [M,K] fp16 row-major. B: [N,K] fp16 row-major. fp32 accumulate.
// CTA tile 256x128 (256 thr, 8 warps of 64x64), K staged 32, 3-stage cp.async.
// outMode: 0 = fp32 Cf; 1 = fp16 Ch; 3 = fp16 Ch with vT scatter.
#define ROWB 80
#define ATILEB (256 * ROWB)         // 20480
#define BTILEB (128 * ROWB)         // 10240
#define STAGEB (ATILEB + BTILEB)    // 30720
#define NSTAGE 3
#define DSMEM_BYTES (NSTAGE * STAGEB)   // 92160

__device__ __forceinline__ void load_stage(
    int tid, uint32_t base,
    const __half* A, int lda, const __half* B, int ldb,
    int m0, int n0, int k0)
{
#pragma unroll
    for (int j = 0; j < 4; j++) {
        int c = tid + j * 256;              // 0..1023
        int row = c >> 2, c4 = c & 3;
        cp16(base + (uint32_t)(row * ROWB + c4 * 16),
             A + (long)(m0 + row) * lda + k0 + c4 * 8);
    }
#pragma unroll
    for (int j = 0; j < 2; j++) {
        int c = tid + j * 256;              // 0..511
        int row = c >> 2, c4 = c & 3;
        cp16(base + ATILEB + (uint32_t)(row * ROWB + c4 * 16),
             B + (long)(n0 + row) * ldb + k0 + c4 * 8);
    }
}

__global__ void __launch_bounds__(256, 1)
gemm_h(const __half* __restrict__ A, int lda,
       const __half* __restrict__ B, int ldb,
       const float* __restrict__ bias,
       float* __restrict__ Cf, __half* __restrict__ Ch,
       int ldc, int K, int relu, int outMode)
{
    extern __shared__ char dsm[];
    uint32_t sb = smem_u32(dsm);

    const int m0 = blockIdx.y * 256, n0 = blockIdx.x * 128;
    const int tid  = threadIdx.x;
    const int lane = tid & 31, wid = tid >> 5;
    const int mW = (wid & 3) * 64, nW = (wid >> 2) * 64;

    const uint32_t aRowOff = (uint32_t)((mW + (lane & 15)) * ROWB + (lane >> 4) * 16);
    const uint32_t bRowOff = (uint32_t)((nW + (lane & 7) + ((lane >> 4) * 8)) * ROWB
                                        + ((lane >> 3) & 1) * 16);

    const int nst = K >> 5;
    float acc[4][8][4] = {};

    load_stage(tid, sb, A, lda, B, ldb, m0, n0, 0);
    CP_COMMIT();
    if (nst > 1) load_stage(tid, sb + STAGEB, A, lda, B, ldb, m0, n0, 32);
    CP_COMMIT();

    int slot = 0;
    for (int s = 0; s < nst; s++) {
        CP_WAIT(1);
        __syncthreads();
        uint32_t cur = sb + (uint32_t)slot * STAGEB;

#pragma unroll
        for (int kk = 0; kk < 2; kk++) {
            const uint32_t kb = kk * 32;
            uint32_t a[4][4], b[4][4];
#pragma unroll
            for (int mt = 0; mt < 4; mt++)
                ldsm4(a[mt], cur + aRowOff + mt * (16 * ROWB) + kb);
#pragma unroll
            for (int nh = 0; nh < 4; nh++)
                ldsm4(b[nh], cur + ATILEB + bRowOff + nh * (16 * ROWB) + kb);
#pragma unroll
            for (int nh = 0; nh < 4; nh++)
#pragma unroll
                for (int hf = 0; hf < 2; hf++)
#pragma unroll
                    for (int mt = 0; mt < 4; mt++)
                        mma16816(acc[mt][nh*2+hf], a[mt], b[nh] + 2*hf);
        }
        __syncthreads();
        if (s + 2 < nst) {
            int nslot = slot + 2; if (nslot >= NSTAGE) nslot -= NSTAGE;
            load_stage(tid, sb + (uint32_t)nslot * STAGEB,
                       A, lda, B, ldb, m0, n0, (s + 2) * 32);
        }
        CP_COMMIT();
        slot++; if (slot == NSTAGE) slot = 0;
    }

    // ---- epilogue ----
    const int rIn = lane >> 2, cIn = (lane & 3) * 2;
#pragma unroll
    for (int mt = 0; mt < 4; mt++) {
#pragma unroll
        for (int nt = 0; nt < 8; nt++) {
            float* a4 = acc[mt][nt];
            int col = n0 + nW + nt*8 + cIn;
            long r0 = (long)m0 + mW + mt*16 + rIn;
            long r1 = r0 + 8;
            float v0 = a4[0], v1 = a4[1], v2 = a4[2], v3 = a4[3];
            if (bias) {
                float b0_ = bias[col], b1_ = bias[col+1];
                v0 += b0_; v1 += b1_; v2 += b0_; v3 += b1_;
            }
            if (relu) {
                v0 = fmaxf(v0,0.f); v1 = fmaxf(v1,0.f);
                v2 = fmaxf(v2,0.f); v3 = fmaxf(v3,0.f);
            }
            if (outMode == 0) {
                *(float2*)(Cf + r0*ldc + col) = make_float2(v0, v1);
                *(float2*)(Cf + r1*ldc + col) = make_float2(v2, v3);
            } else if (outMode == 1) {
                *(__half2*)(Ch + r0*ldc + col) = __floats2half2_rn(v0, v1);
                *(__half2*)(Ch + r1*ldc + col) = __floats2half2_rn(v2, v3);
            } else { // 3: vT scatter
                int b0i = (int)(r0 >> 10), s0 = (int)(r0 & 1023);
                int b1i = (int)(r1 >> 10), s1 = (int)(r1 & 1023);
                int h = col >> 7, dk = col & 127;
                Ch[((long)((b0i*Hh + h)*DKk + dk)     << 10) + s0] = __float2half(v0);
                Ch[((long)((b0i*Hh + h)*DKk + dk + 1) << 10) + s0] = __float2half(v1);
                Ch[((long)((b1i*Hh + h)*DKk + dk)     << 10) + s1] = __float2half(v2);
                Ch[((long)((b1i*Hh + h)*DKk + dk + 1) << 10) + s1] = __float2half(v3);
            }
        }
    }
}

// ============ fused flash attention (strict causal, row0 zeroed) ============
// Per CTA: one (b,h) and one 128-row q-block. 8 warps, each owns 16 q-rows.
// Q = K projection (kq_same). K block tile [s][dk], V tile = vT [dk][s].
#define FROWB 272
#define FTILE (128 * FROWB)                 // 34816
#define FL_SMEM (5 * FTILE)                 // Q + 2xK + 2xV = 174080

__device__ __forceinline__ void fl_load(int tid, uint32_t dstK, uint32_t dstV,
                                        const __half* Kb, const __half* Vb,
                                        int s0)
{
#pragma unroll
    for (int j = 0; j < 8; j++) {
        int c = tid + j * 256;              // 0..2047
        int row = c >> 4, cc = c & 15;
        uint32_t off = (uint32_t)(row * FROWB + cc * 16);
        cp16(dstK + off, Kb + (long)(s0 + row) * Dd + cc * 8);
        cp16(dstV + off, Vb + (long)row * Ss + s0 + cc * 8);
    }
}

__global__ void __launch_bounds__(256, 1)
flash_attn(const __half* __restrict__ kh, const __half* __restrict__ vT,
           __half* __restrict__ t1h)
{
    extern __shared__ char dsm[];
    uint32_t sb = smem_u32(dsm);
    uint32_t sQ = sb, sK = sb + FTILE, sV = sb + 3 * FTILE;

    const int q0 = blockIdx.x * 128;
    const int bh = blockIdx.y;
    const int b = bh >> 3, h = bh & 7;
    const __half* Kbase = kh + ((long)b * Ss) * Dd + h * DKk;   // row s
    const __half* Vbase = vT + ((long)bh * DKk) * Ss;           // row dk

    const int tid = threadIdx.x, lane = tid & 31, w = tid >> 5;
    const float isd = 0.08838834764831845f;   // 1/sqrt(128)

    // load Q tile (128 x 128 fp16, rows = q0..q0+127)
#pragma unroll
    for (int j = 0; j < 8; j++) {
        int c = tid + j * 256;
        int row = c >> 4, cc = c & 15;
        cp16(sQ + (uint32_t)(row * FROWB + cc * 16),
             Kbase + (long)(q0 + row) * Dd + cc * 8);
    }
    CP_COMMIT();
    fl_load(tid, sK, sV, Kbase, Vbase, 0);
    CP_COMMIT();

    CP_WAIT(1);          // Q ready (K0/V0 may still be in flight)
    __syncthreads();

    // Q a-fragments held in registers (16 rows x 128 cols per warp)
    uint32_t qf[8][4];
    const uint32_t qAddr = sQ + (uint32_t)((w * 16 + (lane & 15)) * FROWB
                                           + (lane >> 4) * 16);
#pragma unroll
    for (int kk = 0; kk < 8; kk++) ldsm4(qf[kk], qAddr + kk * 32);

    float o[16][4] = {};
    float mS[2] = {-1e30f, -1e30f};
    float lS[2] = {0.f, 0.f};

    const uint32_t bOff = (uint32_t)(((lane & 7) + ((lane >> 4) * 8)) * FROWB
                                     + ((lane >> 3) & 1) * 16);
    const int nkb = q0 / 128 + 1;

    for (int kb = 0; kb < nkb; kb++) {
        if (kb + 1 < nkb)
            fl_load(tid, sK + (uint32_t)((kb + 1) & 1) * FTILE,
                    sV + (uint32_t)((kb + 1) & 1) * FTILE,
                    Kbase, Vbase, (kb + 1) * 128);
        CP_COMMIT();
        CP_WAIT(1);
        __syncthreads();
        uint32_t curK = sK + (uint32_t)(kb & 1) * FTILE;
        uint32_t curV = sV + (uint32_t)(kb & 1) * FTILE;

        // ---- S = Q @ Kblk^T ----
        float s[16][4] = {};
#pragma unroll
        for (int kk = 0; kk < 8; kk++) {
            uint32_t bf[8][4];
#pragma unroll
            for (int p = 0; p < 8; p++)
                ldsm4(bf[p], curK + bOff + p * (16 * FROWB) + kk * 32);
#pragma unroll
            for (int p = 0; p < 8; p++) {
                mma16816(s[2*p],   qf[kk], bf[p]);
                mma16816(s[2*p+1], qf[kk], bf[p] + 2);
            }
        }
#pragma unroll
        for (int nt = 0; nt < 16; nt++) {
            s[nt][0] *= isd; s[nt][1] *= isd; s[nt][2] *= isd; s[nt][3] *= isd;
        }

        // strict causal mask on diagonal block (col_global < row_global)
        if (kb == nkb - 1) {
            int rA = q0 + w * 16 + (lane >> 2);
            int rB = rA + 8;
            int cb = kb * 128 + (lane & 3) * 2;
#pragma unroll
            for (int nt = 0; nt < 16; nt++) {
                int c0 = cb + nt * 8, c1 = c0 + 1;
                if (c0 >= rA) s[nt][0] = -1e30f;
                if (c1 >= rA) s[nt][1] = -1e30f;
                if (c0 >= rB) s[nt][2] = -1e30f;
                if (c1 >= rB) s[nt][3] = -1e30f;
            }
        }

        // ---- online softmax ----
        float rAm = -1e30f, rBm = -1e30f;
#pragma unroll
        for (int nt = 0; nt < 16; nt++) {
            rAm = fmaxf(rAm, fmaxf(s[nt][0], s[nt][1]));
            rBm = fmaxf(rBm, fmaxf(s[nt][2], s[nt][3]));
        }
        rAm = fmaxf(rAm, __shfl_xor_sync(0xFFFFFFFFu, rAm, 1));
        rAm = fmaxf(rAm, __shfl_xor_sync(0xFFFFFFFFu, rAm, 2));
        rBm = fmaxf(rBm, __shfl_xor_sync(0xFFFFFFFFu, rBm, 1));
        rBm = fmaxf(rBm, __shfl_xor_sync(0xFFFFFFFFu, rBm, 2));

        float mA = fmaxf(mS[0], rAm), mB = fmaxf(mS[1], rBm);
        float aA = __expf(mS[0] - mA), aB = __expf(mS[1] - mB);
        mS[0] = mA; mS[1] = mB;

        float sumA = 0.f, sumB = 0.f;
        uint32_t pf[8][4];
#pragma unroll
        for (int j = 0; j < 8; j++) {
            float e0 = __expf(s[2*j][0]   - mA), e1 = __expf(s[2*j][1]   - mA);
            float e2 = __expf(s[2*j][2]   - mB), e3 = __expf(s[2*j][3]   - mB);
            float f0 = __expf(s[2*j+1][0] - mA), f1 = __expf(s[2*j+1][1] - mA);
            float f2 = __expf(s[2*j+1][2] - mB), f3 = __expf(s[2*j+1][3] - mB);
            sumA += e0 + e1 + f0 + f1;
            sumB += e2 + e3 + f2 + f3;
            pf[j][0] = h2u(e0, e1); pf[j][1] = h2u(e2, e3);
            pf[j][2] = h2u(f0, f1); pf[j][3] = h2u(f2, f3);
        }
        sumA += __shfl_xor_sync(0xFFFFFFFFu, sumA, 1);
        sumA += __shfl_xor_sync(0xFFFFFFFFu, sumA, 2);
        sumB += __shfl_xor_sync(0xFFFFFFFFu, sumB, 1);
        sumB += __shfl_xor_sync(0xFFFFFFFFu, sumB, 2);
        lS[0] = lS[0] * aA + sumA;
        lS[1] = lS[1] * aB + sumB;

#pragma unroll
        for (int nt = 0; nt < 16; nt++) {
            o[nt][0] *= aA; o[nt][1] *= aA; o[nt][2] *= aB; o[nt][3] *= aB;
        }

        // ---- O += P @ Vblk ----
#pragma unroll
        for (int j = 0; j < 8; j++) {
            uint32_t vf[8][4];
#pragma unroll
            for (int p = 0; p < 8; p++)
                ldsm4(vf[p], curV + bOff + p * (16 * FROWB) + j * 32);
#pragma unroll
            for (int p = 0; p < 8; p++) {
                mma16816(o[2*p],   pf[j], vf[p]);
                mma16816(o[2*p+1], pf[j], vf[p] + 2);
            }
        }
        __syncthreads();   // done reading this slot before next prefetch reuses it
    }

    // ---- epilogue: divide by row sums, zero global row 0 ----
    int rowA = q0 + w * 16 + (lane >> 2);
    int rowB = rowA + 8;
    float invA = (rowA == 0) ? 0.f : 1.f / lS[0];
    float invB = 1.f / lS[1];
    __half* oA = t1h + ((long)b * Ss + rowA) * Dd + h * DKk + (lane & 3) * 2;
    __half* oB = t1h + ((long)b * Ss + rowB) * Dd + h * DKk + (lane & 3) * 2;
#pragma unroll
    for (int nt = 0; nt < 16; nt++) {
        *(__half2*)(oA + nt * 8) = __floats2half2_rn(o[nt][0]*invA, o[nt][1]*invA);
        *(__half2*)(oB + nt * 8) = __floats2half2_rn(o[nt][2]*invB, o[nt][3]*invB);
    }
}

// ---------------- residual add + LayerNorm (fp32 out + optional fp16) -------
__global__ void ln_res(const float* __restrict__ x, const float* __restrict__ t,
                       const float* __restrict__ g, const float* __restrict__ b,
                       float* __restrict__ out, __half* __restrict__ outh)
{
    __shared__ float red[256];
    long row = blockIdx.x;
    int tid = threadIdx.x;
    const float* xp = x + row * Dd;
    const float* tp = t + row * Dd;

    float v[4];
    float s = 0.f;
#pragma unroll
    for (int q = 0; q < 4; q++) {
        int c = tid + q * 256;
        v[q] = xp[c] + tp[c];
        s += v[q];
    }
    red[tid] = s; __syncthreads();
    for (int off = 128; off > 0; off >>= 1) {
        if (tid < off) red[tid] += red[tid + off];
        __syncthreads();
    }
    float mean = red[0] * (1.f / Dd);
    __syncthreads();

    float s2 = 0.f;
#pragma unroll
    for (int q = 0; q < 4; q++) {
        float d = v[q] - mean;
        s2 += d * d;
    }
    red[tid] = s2; __syncthreads();
    for (int off = 128; off > 0; off >>= 1) {
        if (tid < off) red[tid] += red[tid + off];
        __syncthreads();
    }
    float inv = rsqrtf(red[0] * (1.f / Dd) + 1e-5f);

#pragma unroll
    for (int q = 0; q < 4; q++) {
        int c = tid + q * 256;
        float val = (v[q] - mean) * inv * g[c] + b[c];
        out[row * Dd + c] = val;
        if (outh) outh[row * Dd + c] = __float2half(val);
    }
}

// ---------------- driver ----------------------------------------------------
extern "C" void kernel_launch(void* const* d_in, const int* in_sizes, int n_in,
                              void* d_out, int out_size)
{
    const float* q_embed = (const float*)d_in[0];
    const float* qa_embed= (const float*)d_in[1];
    const float* pos     = (const float*)d_in[2];
    const float* Wk  = (const float*)d_in[3];
    const float* bk  = (const float*)d_in[4];
    const float* Wv  = (const float*)d_in[5];
    const float* bv  = (const float*)d_in[6];
    const float* Wo  = (const float*)d_in[7];
    const float* bo  = (const float*)d_in[8];
    const float* ln1g= (const float*)d_in[9];
    const float* ln1b= (const float*)d_in[10];
    const float* W1  = (const float*)d_in[11];
    const float* b1  = (const float*)d_in[12];
    const float* W2  = (const float*)d_in[13];
    const float* b2  = (const float*)d_in[14];
    const float* ln2g= (const float*)d_in[15];
    const float* ln2b= (const float*)d_in[16];
    float* out = (float*)d_out;

    float *x, *t2;
    __half *xh, *yh, *kh, *vh, *t1h, *ffh;
    __half *wk, *wv, *wo, *w1, *w2;
    cudaGetSymbolAddress((void**)&x,   g_x);
    cudaGetSymbolAddress((void**)&t2,  g_t2);
    cudaGetSymbolAddress((void**)&xh,  g_xh);
    cudaGetSymbolAddress((void**)&yh,  g_yh);
    cudaGetSymbolAddress((void**)&kh,  g_kh);
    cudaGetSymbolAddress((void**)&vh,  g_vh);
    cudaGetSymbolAddress((void**)&t1h, g_t1h);
    cudaGetSymbolAddress((void**)&ffh, g_ffh);
    cudaGetSymbolAddress((void**)&wk,  g_wk);
    cudaGetSymbolAddress((void**)&wv,  g_wv);
    cudaGetSymbolAddress((void**)&wo,  g_wo);
    cudaGetSymbolAddress((void**)&w1,  g_w1);
    cudaGetSymbolAddress((void**)&w2,  g_w2);

    cudaFuncSetAttribute(gemm_h, cudaFuncAttributeMaxDynamicSharedMemorySize,
                         DSMEM_BYTES);
    cudaFuncSetAttribute(flash_attn, cudaFuncAttributeMaxDynamicSharedMemorySize,
                         FL_SMEM);

    add_pos_kernel<<<(Bb*Ss*Dd)/256, 256>>>(q_embed, qa_embed, pos, x, xh, yh);

    for (int l = 0; l < Ll; l++) {
        const float* bkl_ = bk + (long)l*Dd;
        const float* bvl_ = bv + (long)l*Dd;
        const float* bol_ = bo + (long)l*Dd;
        const float* b1l_ = b1 + (long)l*FFf;
        const float* b2l_ = b2 + (long)l*Dd;

        // convert this layer's weights to fp16
        wconv<<<(Dd*Dd)/256, 256>>>(Wk + (long)l*Dd*Dd, wk, Dd*Dd);
        wconv<<<(Dd*Dd)/256, 256>>>(Wv + (long)l*Dd*Dd, wv, Dd*Dd);
        wconv<<<(Dd*Dd)/256, 256>>>(Wo + (long)l*Dd*Dd, wo, Dd*Dd);
        wconv<<<(FFf*Dd)/256, 256>>>(W1 + (long)l*FFf*Dd, w1, FFf*Dd);
        wconv<<<(Dd*FFf)/256, 256>>>(W2 + (long)l*Dd*FFf, w2, Dd*FFf);

        dim3 gP (Dd/128,  (Bb*Ss)/256);
        dim3 gF1(FFf/128, (Bb*Ss)/256);
        dim3 gF2(Dd/128,  (Bb*Ss)/256);
        dim3 gFA(Ss/128,  Bb*Hh);

        // K = x @ Wk^T + bk  -> fp16 (q == k)
        gemm_h<<<gP, 256, DSMEM_BYTES>>>(xh, Dd, wk, Dd, bkl_,
            nullptr, kh, Dd, Dd, 0, 1);
        // vT = (y @ Wv^T + bv)^T scatter -> fp16
        gemm_h<<<gP, 256, DSMEM_BYTES>>>(yh, Dd, wv, Dd, bvl_,
            nullptr, vh, Dd, Dd, 0, 3);
        // fused attention: scores + masked softmax + P@V -> t1h
        flash_attn<<<gFA, 256, FL_SMEM>>>(kh, vh, t1h);
        // t2 = t1 @ Wo^T + bo -> fp32
        gemm_h<<<gP, 256, DSMEM_BYTES>>>(t1h, Dd, wo, Dd, bol_,
            t2, nullptr, Dd, Dd, 0, 0);
        // x = LN(x + t2) -> fp32 + fp16
        ln_res<<<Bb*Ss, 256>>>(x, t2, ln1g + (long)l*Dd, ln1b + (long)l*Dd, x, xh);
        // ff = relu(x @ W1^T + b1) -> fp16
        gemm_h<<<gF1, 256, DSMEM_BYTES>>>(xh, Dd, w1, Dd, b1l_,
            nullptr, ffh, FFf, Dd, 1, 1);
        // t2 = ff @ W2^T + b2 -> fp32
        gemm_h<<<gF2, 256, DSMEM_BYTES>>>(ffh, FFf, w2, FFf, b2l_,
            t2, nullptr, Dd, FFf, 0, 0);
        // x = LN(x + t2); final layer -> d_out (fp32 only)
        float* xout = (l == Ll - 1) ? out : x;
        __half* xhout = (l == Ll - 1) ? nullptr : xh;
        ln_res<<<Bb*Ss, 256>>>(x, t2, ln2g + (long)l*Dd, ln2b + (long)l*Dd,
                               xout, xhout);
    }
}

// round 7
// speedup vs baseline: 7.4912x; 1.0850x over previous
#include <cuda_runtime.h>
#include <cuda_fp16.h>
#include <math.h>
#include <stdint.h>

// Problem constants
#define Bb 8
#define Ss 1024
#define Dd 1024
#define Hh 8
#define DKk 128
#define FFf 4096
#define Ll 2

// ---------------- scratch (device globals; no allocation allowed) ----------
__device__ float  g_x [Bb*Ss*Dd];                 // fp32 activation (residual)
__device__ float  g_t2[Bb*Ss*Dd];                 // fp32 branch output
__device__ __half g_xh [Bb*Ss*Dd];
__device__ __half g_yh [Bb*Ss*Dd];
__device__ __half g_kh [Bb*Ss*Dd];
__device__ __half g_vh [Bb*Ss*Dd];                // vT [b,h,dk,s]
__device__ __half g_t1h[Bb*Ss*Dd];
__device__ __half g_ffh[Bb*Ss*FFf];
// fp16 weights (converted per layer)
__device__ __half g_wk[Dd*Dd];
__device__ __half g_wv[Dd*Dd];
__device__ __half g_wo[Dd*Dd];
__device__ __half g_w1[FFf*Dd];
__device__ __half g_w2[Dd*FFf];

// ======================= helpers ============================================
__device__ __forceinline__ uint32_t smem_u32(const void* p) {
    uint32_t a;
    asm("{ .reg .u64 t; cvta.to.shared.u64 t, %1; cvt.u32.u64 %0, t; }"
        : "=r"(a) : "l"(p));
    return a;
}

__device__ __forceinline__ void ldsm4(uint32_t* r, uint32_t addr) {
    asm volatile("ldmatrix.sync.aligned.m8n8.x4.shared.b16 {%0,%1,%2,%3}, [%4];"
        : "=r"(r[0]), "=r"(r[1]), "=r"(r[2]), "=r"(r[3]) : "r"(addr));
}

__device__ __forceinline__ void mma16816(float* c, const uint32_t* a,
                                         const uint32_t* b) {
    asm volatile(
        "mma.sync.aligned.m16n8k16.row.col.f32.f16.f16.f32 "
        "{%0,%1,%2,%3}, {%4,%5,%6,%7}, {%8,%9}, {%0,%1,%2,%3};"
        : "+f"(c[0]), "+f"(c[1]), "+f"(c[2]), "+f"(c[3])
        : "r"(a[0]), "r"(a[1]), "r"(a[2]), "r"(a[3]), "r"(b[0]), "r"(b[1]));
}

__device__ __forceinline__ void cp16(uint32_t dst, const void* src) {
    asm volatile("cp.async.cg.shared.global [%0], [%1], 16;"
        :: "r"(dst), "l"(src));
}
#define CP_COMMIT() asm volatile("cp.async.commit_group;" ::: "memory")
#define CP_WAIT(n)  asm volatile("cp.async.wait_group %0;" :: "n"(n) : "memory")

__device__ __forceinline__ uint32_t h2u(float a, float b) {
    __half2 h = __floats2half2_rn(a, b);
    return *(uint32_t*)&h;
}

// ---------------- small elementwise kernels ---------------------------------
__global__ void add_pos_kernel(const float* __restrict__ q,
                               const float* __restrict__ qa,
                               const float* __restrict__ pe,
                               float* __restrict__ x,
                               __half* __restrict__ xh,
                               __half* __restrict__ yh)
{
    int idx = blockIdx.x * 256 + threadIdx.x;
    int sd  = idx & (Ss*Dd - 1);
    float p = pe[sd];
    float xv = q[idx] + p;
    x[idx]  = xv;
    xh[idx] = __float2half(xv);
    yh[idx] = __float2half(qa[idx] + p);
}

// Convert all 5 weight matrices of one layer in a single launch
// (keeps GEMMs at stable launch indices for ncu's -s 5 -c 1 capture).
#define NW1 (Dd*Dd)
#define NWF (FFf*Dd)
__global__ void wconv_all(const float* __restrict__ Wk,
                          const float* __restrict__ Wv,
                          const float* __restrict__ Wo,
                          const float* __restrict__ W1,
                          const float* __restrict__ W2,
                          __half* __restrict__ wk, __half* __restrict__ wv,
                          __half* __restrict__ wo, __half* __restrict__ w1,
                          __half* __restrict__ w2)
{
    int i = blockIdx.x * 256 + threadIdx.x;
    if (i < NW1)              wk[i] = __float2half(Wk[i]);
    else if (i < 2*NW1)       wv[i - NW1]   = __float2half(Wv[i - NW1]);
    else if (i < 3*NW1)       wo[i - 2*NW1] = __float2half(Wo[i - 2*NW1]);
    else if (i < 3*NW1 + NWF) w1[i - 3*NW1] = __float2half(W1[i - 3*NW1]);
    else                      w2[i - 3*NW1 - NWF] = __float2half(W2[i - 3*NW1 - NWF]);
}
#define WCONV_TOTAL (3*NW1 + 2*NWF)

// ============ fp16 GEMM: C = A * B^T (+bias)(+relu) =========================
// A: [M,K] fp16 row-major. B: [N,K] fp16 row-major. fp32 accumulate.
// CTA tile 256x128 (8 warps of 64x64), K staged 64 wide, 3-stage cp.async ring,
// ONE __syncthreads per stage, ldsm fragments double-buffered across k16 steps.
// outMode: 0 = fp32 Cf; 1 = fp16 Ch; 3 = fp16 Ch with vT scatter.
#define ROWB 144                    // 64 halves (128B) + 16B pad
#define ATILEB (256 * ROWB)         // 36864
#define BTILEB (128 * ROWB)         // 18432
#define STAGEB (ATILEB + BTILEB)    // 55296
#define NSTAGE 3
#define DSMEM_BYTES (NSTAGE * STAGEB)   // 165888

__device__ __forceinline__ void load_stage(
    int tid, uint32_t base,
    const __half* A, int lda, const __half* B, int ldb,
    int m0, int n0, int k0)
{
#pragma unroll
    for (int j = 0; j < 8; j++) {
        int c = tid + j * 256;              // 0..2047
        int row = c >> 3, c8 = c & 7;
        cp16(base + (uint32_t)(row * ROWB + c8 * 16),
             A + (long)(m0 + row) * lda + k0 + c8 * 8);
    }
#pragma unroll
    for (int j = 0; j < 4; j++) {
        int c = tid + j * 256;              // 0..1023
        int row = c >> 3, c8 = c & 7;
        cp16(base + ATILEB + (uint32_t)(row * ROWB + c8 * 16),
             B + (long)(n0 + row) * ldb + k0 + c8 * 8);
    }
}

__global__ void __launch_bounds__(256)
gemm_h(const __half* __restrict__ A, int lda,
       const __half* __restrict__ B, int ldb,
       const float* __restrict__ bias,
       float* __restrict__ Cf, __half* __restrict__ Ch,
       int ldc, int K, int relu, int outMode)
{
    extern __shared__ char dsm[];
    uint32_t sb = smem_u32(dsm);

    const int m0 = blockIdx.y * 256, n0 = blockIdx.x * 128;
    const int tid  = threadIdx.x;
    const int lane = tid & 31, wid = tid >> 5;
    const int mW = (wid & 3) * 64, nW = (wid >> 2) * 64;

    const uint32_t aRowOff = (uint32_t)((mW + (lane & 15)) * ROWB + (lane >> 4) * 16);
    const uint32_t bRowOff = (uint32_t)((nW + (lane & 7) + ((lane >> 4) * 8)) * ROWB
                                        + ((lane >> 3) & 1) * 16);

    const int nst = K >> 6;
    float acc[4][8][4] = {};
    uint32_t a[2][4][4], b[2][4][4];

    load_stage(tid, sb, A, lda, B, ldb, m0, n0, 0);
    CP_COMMIT();
    if (nst > 1) load_stage(tid, sb + STAGEB, A, lda, B, ldb, m0, n0, 64);
    CP_COMMIT();

    int slot = 0;
    for (int s = 0; s < nst; s++) {
        CP_WAIT(1);
        __syncthreads();            // single barrier per stage
        uint32_t cur = sb + (uint32_t)slot * STAGEB;

        // prime kk=0 fragments
#pragma unroll
        for (int mt = 0; mt < 4; mt++)
            ldsm4(a[0][mt], cur + aRowOff + mt * (16 * ROWB));
#pragma unroll
        for (int nh = 0; nh < 4; nh++)
            ldsm4(b[0][nh], cur + ATILEB + bRowOff + nh * (16 * ROWB));

        // prefetch stage s+2 into slot (s+2)%NSTAGE — safe: top barrier proved
        // every warp finished reading that slot in stage s-1.
        if (s + 2 < nst) {
            int nslot = slot + 2; if (nslot >= NSTAGE) nslot -= NSTAGE;
            load_stage(tid, sb + (uint32_t)nslot * STAGEB,
                       A, lda, B, ldb, m0, n0, (s + 2) * 64);
        }
        CP_COMMIT();

#pragma unroll
        for (int kk = 0; kk < 4; kk++) {
            const int cb = kk & 1;
            if (kk < 3) {           // load kk+1 frags while MMA'ing kk
                const int nb = cb ^ 1;
                const uint32_t kb = (uint32_t)(kk + 1) * 32;
#pragma unroll
                for (int mt = 0; mt < 4; mt++)
                    ldsm4(a[nb][mt], cur + aRowOff + mt * (16 * ROWB) + kb);
#pragma unroll
                for (int nh = 0; nh < 4; nh++)
                    ldsm4(b[nb][nh], cur + ATILEB + bRowOff + nh * (16 * ROWB) + kb);
            }
#pragma unroll
            for (int nh = 0; nh < 4; nh++)
#pragma unroll
                for (int hf = 0; hf < 2; hf++)
#pragma unroll
                    for (int mt = 0; mt < 4; mt++)
                        mma16816(acc[mt][nh*2+hf], a[cb][mt], b[cb][nh] + 2*hf);
        }
        slot++; if (slot == NSTAGE) slot = 0;
    }

    // ---- epilogue ----
    const int rIn = lane >> 2, cIn = (lane & 3) * 2;
#pragma unroll
    for (int mt = 0; mt < 4; mt++) {
#pragma unroll
        for (int nt = 0; nt < 8; nt++) {
            float* a4 = acc[mt][nt];
            int col = n0 + nW + nt*8 + cIn;
            long r0 = (long)m0 + mW + mt*16 + rIn;
            long r1 = r0 + 8;
            float v0 = a4[0], v1 = a4[1], v2 = a4[2], v3 = a4[3];
            if (bias) {
                float b0_ = bias[col], b1_ = bias[col+1];
                v0 += b0_; v1 += b1_; v2 += b0_; v3 += b1_;
            }
            if (relu) {
                v0 = fmaxf(v0,0.f); v1 = fmaxf(v1,0.f);
                v2 = fmaxf(v2,0.f); v3 = fmaxf(v3,0.f);
            }
            if (outMode == 0) {
                *(float2*)(Cf + r0*ldc + col) = make_float2(v0, v1);
                *(float2*)(Cf + r1*ldc + col) = make_float2(v2, v3);
            } else if (outMode == 1) {
                *(__half2*)(Ch + r0*ldc + col) = __floats2half2_rn(v0, v1);
                *(__half2*)(Ch + r1*ldc + col) = __floats2half2_rn(v2, v3);
            } else { // 3: vT scatter
                int b0i = (int)(r0 >> 10), s0 = (int)(r0 & 1023);
                int b1i = (int)(r1 >> 10), s1 = (int)(r1 & 1023);
                int h = col >> 7, dk = col & 127;
                Ch[((long)((b0i*Hh + h)*DKk + dk)     << 10) + s0] = __float2half(v0);
                Ch[((long)((b0i*Hh + h)*DKk + dk + 1) << 10) + s0] = __float2half(v1);
                Ch[((long)((b1i*Hh + h)*DKk + dk)     << 10) + s1] = __float2half(v2);
                Ch[((long)((b1i*Hh + h)*DKk + dk + 1) << 10) + s1] = __float2half(v3);
            }
        }
    }
}

// ============ fused flash attention (strict causal, row0 zeroed) ============
#define FROWB 272
#define FTILE (128 * FROWB)                 // 34816
#define FL_SMEM (5 * FTILE)                 // Q + 2xK + 2xV = 174080

__device__ __forceinline__ void fl_load(int tid, uint32_t dstK, uint32_t dstV,
                                        const __half* Kb, const __half* Vb,
                                        int s0)
{
#pragma unroll
    for (int j = 0; j < 8; j++) {
        int c = tid + j * 256;              // 0..2047
        int row = c >> 4, cc = c & 15;
        uint32_t off = (uint32_t)(row * FROWB + cc * 16);
        cp16(dstK + off, Kb + (long)(s0 + row) * Dd + cc * 8);
        cp16(dstV + off, Vb + (long)row * Ss + s0 + cc * 8);
    }
}

__global__ void __launch_bounds__(256, 1)
flash_attn(const __half* __restrict__ kh, const __half* __restrict__ vT,
           __half* __restrict__ t1h)
{
    extern __shared__ char dsm[];
    uint32_t sb = smem_u32(dsm);
    uint32_t sQ = sb, sK = sb + FTILE, sV = sb + 3 * FTILE;

    const int q0 = blockIdx.x * 128;
    const int bh = blockIdx.y;
    const int b = bh >> 3, h = bh & 7;
    const __half* Kbase = kh + ((long)b * Ss) * Dd + h * DKk;
    const __half* Vbase = vT + ((long)bh * DKk) * Ss;

    const int tid = threadIdx.x, lane = tid & 31, w = tid >> 5;
    const float isd = 0.08838834764831845f;

#pragma unroll
    for (int j = 0; j < 8; j++) {
        int c = tid + j * 256;
        int row = c >> 4, cc = c & 15;
        cp16(sQ + (uint32_t)(row * FROWB + cc * 16),
             Kbase + (long)(q0 + row) * Dd + cc * 8);
    }
    CP_COMMIT();
    fl_load(tid, sK, sV, Kbase, Vbase, 0);
    CP_COMMIT();

    CP_WAIT(1);
    __syncthreads();

    uint32_t qf[8][4];
    const uint32_t qAddr = sQ + (uint32_t)((w * 16 + (lane & 15)) * FROWB
                                           + (lane >> 4) * 16);
#pragma unroll
    for (int kk = 0; kk < 8; kk++) ldsm4(qf[kk], qAddr + kk * 32);

    float o[16][4] = {};
    float mS[2] = {-1e30f, -1e30f};
    float lS[2] = {0.f, 0.f};

    const uint32_t bOff = (uint32_t)(((lane & 7) + ((lane >> 4) * 8)) * FROWB
                                     + ((lane >> 3) & 1) * 16);
    const int nkb = q0 / 128 + 1;

    for (int kb = 0; kb < nkb; kb++) {
        if (kb + 1 < nkb)
            fl_load(tid, sK + (uint32_t)((kb + 1) & 1) * FTILE,
                    sV + (uint32_t)((kb + 1) & 1) * FTILE,
                    Kbase, Vbase, (kb + 1) * 128);
        CP_COMMIT();
        CP_WAIT(1);
        __syncthreads();
        uint32_t curK = sK + (uint32_t)(kb & 1) * FTILE;
        uint32_t curV = sV + (uint32_t)(kb & 1) * FTILE;

        float s[16][4] = {};
#pragma unroll
        for (int kk = 0; kk < 8; kk++) {
            uint32_t bf[8][4];
#pragma unroll
            for (int p = 0; p < 8; p++)
                ldsm4(bf[p], curK + bOff + p * (16 * FROWB) + kk * 32);
#pragma unroll
            for (int p = 0; p < 8; p++) {
                mma16816(s[2*p],   qf[kk], bf[p]);
                mma16816(s[2*p+1], qf[kk], bf[p] + 2);
            }
        }
#pragma unroll
        for (int nt = 0; nt < 16; nt++) {
            s[nt][0] *= isd; s[nt][1] *= isd; s[nt][2] *= isd; s[nt][3] *= isd;
        }

        if (kb == nkb - 1) {
            int rA = q0 + w * 16 + (lane >> 2);
            int rB = rA + 8;
            int cb = kb * 128 + (lane & 3) * 2;
#pragma unroll
            for (int nt = 0; nt < 16; nt++) {
                int c0 = cb + nt * 8, c1 = c0 + 1;
                if (c0 >= rA) s[nt][0] = -1e30f;
                if (c1 >= rA) s[nt][1] = -1e30f;
                if (c0 >= rB) s[nt][2] = -1e30f;
                if (c1 >= rB) s[nt][3] = -1e30f;
            }
        }

        float rAm = -1e30f, rBm = -1e30f;
#pragma unroll
        for (int nt = 0; nt < 16; nt++) {
            rAm = fmaxf(rAm, fmaxf(s[nt][0], s[nt][1]));
            rBm = fmaxf(rBm, fmaxf(s[nt][2], s[nt][3]));
        }
        rAm = fmaxf(rAm, __shfl_xor_sync(0xFFFFFFFFu, rAm, 1));
        rAm = fmaxf(rAm, __shfl_xor_sync(0xFFFFFFFFu, rAm, 2));
        rBm = fmaxf(rBm, __shfl_xor_sync(0xFFFFFFFFu, rBm, 1));
        rBm = fmaxf(rBm, __shfl_xor_sync(0xFFFFFFFFu, rBm, 2));

        float mA = fmaxf(mS[0], rAm), mB = fmaxf(mS[1], rBm);
        float aA = __expf(mS[0] - mA), aB = __expf(mS[1] - mB);
        mS[0] = mA; mS[1] = mB;

        float sumA = 0.f, sumB = 0.f;
        uint32_t pf[8][4];
#pragma unroll
        for (int j = 0; j < 8; j++) {
            float e0 = __expf(s[2*j][0]   - mA), e1 = __expf(s[2*j][1]   - mA);
            float e2 = __expf(s[2*j][2]   - mB), e3 = __expf(s[2*j][3]   - mB);
            float f0 = __expf(s[2*j+1][0] - mA), f1 = __expf(s[2*j+1][1] - mA);
            float f2 = __expf(s[2*j+1][2] - mB), f3 = __expf(s[2*j+1][3] - mB);
            sumA += e0 + e1 + f0 + f1;
            sumB += e2 + e3 + f2 + f3;
            pf[j][0] = h2u(e0, e1); pf[j][1] = h2u(e2, e3);
            pf[j][2] = h2u(f0, f1); pf[j][3] = h2u(f2, f3);
        }
        sumA += __shfl_xor_sync(0xFFFFFFFFu, sumA, 1);
        sumA += __shfl_xor_sync(0xFFFFFFFFu, sumA, 2);
        sumB += __shfl_xor_sync(0xFFFFFFFFu, sumB, 1);
        sumB += __shfl_xor_sync(0xFFFFFFFFu, sumB, 2);
        lS[0] = lS[0] * aA + sumA;
        lS[1] = lS[1] * aB + sumB;

#pragma unroll
        for (int nt = 0; nt < 16; nt++) {
            o[nt][0] *= aA; o[nt][1] *= aA; o[nt][2] *= aB; o[nt][3] *= aB;
        }

#pragma unroll
        for (int j = 0; j < 8; j++) {
            uint32_t vf[8][4];
#pragma unroll
            for (int p = 0; p < 8; p++)
                ldsm4(vf[p], curV + bOff + p * (16 * FROWB) + j * 32);
#pragma unroll
            for (int p = 0; p < 8; p++) {
                mma16816(o[2*p],   pf[j], vf[p]);
                mma16816(o[2*p+1], pf[j], vf[p] + 2);
            }
        }
        __syncthreads();
    }

    int rowA = q0 + w * 16 + (lane >> 2);
    int rowB = rowA + 8;
    float invA = (rowA == 0) ? 0.f : 1.f / lS[0];
    float invB = 1.f / lS[1];
    __half* oA = t1h + ((long)b * Ss + rowA) * Dd + h * DKk + (lane & 3) * 2;
    __half* oB = t1h + ((long)b * Ss + rowB) * Dd + h * DKk + (lane & 3) * 2;
#pragma unroll
    for (int nt = 0; nt < 16; nt++) {
        *(__half2*)(oA + nt * 8) = __floats2half2_rn(o[nt][0]*invA, o[nt][1]*invA);
        *(__half2*)(oB + nt * 8) = __floats2half2_rn(o[nt][2]*invB, o[nt][3]*invB);
    }
}

// ---------------- residual add + LayerNorm (fp32 out + optional fp16) -------
__global__ void ln_res(const float* __restrict__ x, const float* __restrict__ t,
                       const float* __restrict__ g, const float* __restrict__ b,
                       float* __restrict__ out, __half* __restrict__ outh)
{
    __shared__ float red[256];
    long row = blockIdx.x;
    int tid = threadIdx.x;
    const float* xp = x + row * Dd;
    const float* tp = t + row * Dd;

    float v[4];
    float s = 0.f;
#pragma unroll
    for (int q = 0; q < 4; q++) {
        int c = tid + q * 256;
        v[q] = xp[c] + tp[c];
        s += v[q];
    }
    red[tid] = s; __syncthreads();
    for (int off = 128; off > 0; off >>= 1) {
        if (tid < off) red[tid] += red[tid + off];
        __syncthreads();
    }
    float mean = red[0] * (1.f / Dd);
    __syncthreads();

    float s2 = 0.f;
#pragma unroll
    for (int q = 0; q < 4; q++) {
        float d = v[q] - mean;
        s2 += d * d;
    }
    red[tid] = s2; __syncthreads();
    for (int off = 128; off > 0; off >>= 1) {
        if (tid < off) red[tid] += red[tid + off];
        __syncthreads();
    }
    float inv = rsqrtf(red[0] * (1.f / Dd) + 1e-5f);

#pragma unroll
    for (int q = 0; q < 4; q++) {
        int c = tid + q * 256;
        float val = (v[q] - mean) * inv * g[c] + b[c];
        out[row * Dd + c] = val;
        if (outh) outh[row * Dd + c] = __float2half(val);
    }
}

// ---------------- driver ----------------------------------------------------
extern "C" void kernel_launch(void* const* d_in, const int* in_sizes, int n_in,
                              void* d_out, int out_size)
{
    const float* q_embed = (const float*)d_in[0];
    const float* qa_embed= (const float*)d_in[1];
    const float* pos     = (const float*)d_in[2];
    const float* Wk  = (const float*)d_in[3];
    const float* bk  = (const float*)d_in[4];
    const float* Wv  = (const float*)d_in[5];
    const float* bv  = (const float*)d_in[6];
    const float* Wo  = (const float*)d_in[7];
    const float* bo  = (const float*)d_in[8];
    const float* ln1g= (const float*)d_in[9];
    const float* ln1b= (const float*)d_in[10];
    const float* W1  = (const float*)d_in[11];
    const float* b1  = (const float*)d_in[12];
    const float* W2  = (const float*)d_in[13];
    const float* b2  = (const float*)d_in[14];
    const float* ln2g= (const float*)d_in[15];
    const float* ln2b= (const float*)d_in[16];
    float* out = (float*)d_out;

    float *x, *t2;
    __half *xh, *yh, *kh, *vh, *t1h, *ffh;
    __half *wk, *wv, *wo, *w1, *w2;
    cudaGetSymbolAddress((void**)&x,   g_x);
    cudaGetSymbolAddress((void**)&t2,  g_t2);
    cudaGetSymbolAddress((void**)&xh,  g_xh);
    cudaGetSymbolAddress((void**)&yh,  g_yh);
    cudaGetSymbolAddress((void**)&kh,  g_kh);
    cudaGetSymbolAddress((void**)&vh,  g_vh);
    cudaGetSymbolAddress((void**)&t1h, g_t1h);
    cudaGetSymbolAddress((void**)&ffh, g_ffh);
    cudaGetSymbolAddress((void**)&wk,  g_wk);
    cudaGetSymbolAddress((void**)&wv,  g_wv);
    cudaGetSymbolAddress((void**)&wo,  g_wo);
    cudaGetSymbolAddress((void**)&w1,  g_w1);
    cudaGetSymbolAddress((void**)&w2,  g_w2);

    cudaFuncSetAttribute(gemm_h, cudaFuncAttributeMaxDynamicSharedMemorySize,
                         DSMEM_BYTES);
    cudaFuncSetAttribute(flash_attn, cudaFuncAttributeMaxDynamicSharedMemorySize,
                         FL_SMEM);

    add_pos_kernel<<<(Bb*Ss*Dd)/256, 256>>>(q_embed, qa_embed, pos, x, xh, yh);

    for (int l = 0; l < Ll; l++) {
        const float* bkl_ = bk + (long)l*Dd;
        const float* bvl_ = bv + (long)l*Dd;
        const float* bol_ = bo + (long)l*Dd;
        const float* b1l_ = b1 + (long)l*FFf;
        const float* b2l_ = b2 + (long)l*Dd;

        // one launch: convert all weights for this layer to fp16
        wconv_all<<<(WCONV_TOTAL + 255)/256, 256>>>(
            Wk + (long)l*Dd*Dd, Wv + (long)l*Dd*Dd, Wo + (long)l*Dd*Dd,
            W1 + (long)l*FFf*Dd, W2 + (long)l*Dd*FFf,
            wk, wv, wo, w1, w2);

        dim3 gP (Dd/128,  (Bb*Ss)/256);
        dim3 gF1(FFf/128, (Bb*Ss)/256);
        dim3 gF2(Dd/128,  (Bb*Ss)/256);
        dim3 gFA(Ss/128,  Bb*Hh);

        // K = x @ Wk^T + bk  -> fp16 (q == k)
        gemm_h<<<gP, 256, DSMEM_BYTES>>>(xh, Dd, wk, Dd, bkl_,
            nullptr, kh, Dd, Dd, 0, 1);
        // vT = (y @ Wv^T + bv)^T scatter -> fp16
        gemm_h<<<gP, 256, DSMEM_BYTES>>>(yh, Dd, wv, Dd, bvl_,
            nullptr, vh, Dd, Dd, 0, 3);
        // fused attention: scores + masked softmax + P@V -> t1h
        flash_attn<<<gFA, 256, FL_SMEM>>>(kh, vh, t1h);
        // t2 = t1 @ Wo^T + bo -> fp32      (launch #6 overall: ncu target)
        gemm_h<<<gP, 256, DSMEM_BYTES>>>(t1h, Dd, wo, Dd, bol_,
            t2, nullptr, Dd, Dd, 0, 0);
        // x = LN(x + t2) -> fp32 + fp16
        ln_res<<<Bb*Ss, 256>>>(x, t2, ln1g + (long)l*Dd, ln1b + (long)l*Dd, x, xh);
        // ff = relu(x @ W1^T + b1) -> fp16
        gemm_h<<<gF1, 256, DSMEM_BYTES>>>(xh, Dd, w1, Dd, b1l_,
            nullptr, ffh, FFf, Dd, 1, 1);
        // t2 = ff @ W2^T + b2 -> fp32
        gemm_h<<<gF2, 256, DSMEM_BYTES>>>(ffh, FFf, w2, FFf, b2l_,
            t2, nullptr, Dd, FFf, 0, 0);
        // x = LN(x + t2); final layer -> d_out (fp32 only)
        float* xout = (l == Ll - 1) ? out : x;
        __half* xhout = (l == Ll - 1) ? nullptr : xh;
        ln_res<<<Bb*Ss, 256>>>(x, t2, ln2g + (long)l*Dd, ln2b + (long)l*Dd,
                               xout, xhout);
    }
}

// round 8
// speedup vs baseline: 8.3263x; 1.1115x over previous
#include <cuda_runtime.h>
#include <cuda_fp16.h>
#include <math.h>
#include <stdint.h>

// Problem constants
#define Bb 8
#define Ss 1024
#define Dd 1024
#define Hh 8
#define DKk 128
#define FFf 4096
#define Ll 2

// ---------------- scratch (device globals; no allocation allowed) ----------
__device__ float  g_x [Bb*Ss*Dd];                 // fp32 activation (residual)
__device__ float  g_t2[Bb*Ss*Dd];                 // fp32 branch output
__device__ __half g_xh [Bb*Ss*Dd];
__device__ __half g_yh [Bb*Ss*Dd];
__device__ __half g_kh [Bb*Ss*Dd];
__device__ __half g_vh [Bb*Ss*Dd];                // vT [b,h,dk,s]
__device__ __half g_t1h[Bb*Ss*Dd];
__device__ __half g_ffh[Bb*Ss*FFf];
// fp16 weights (converted per layer)
__device__ __half g_wk[Dd*Dd];
__device__ __half g_wv[Dd*Dd];
__device__ __half g_wo[Dd*Dd];
__device__ __half g_w1[FFf*Dd];
__device__ __half g_w2[Dd*FFf];

// ======================= helpers ============================================
__device__ __forceinline__ uint32_t smem_u32(const void* p) {
    uint32_t a;
    asm("{ .reg .u64 t; cvta.to.shared.u64 t, %1; cvt.u32.u64 %0, t; }"
        : "=r"(a) : "l"(p));
    return a;
}

__device__ __forceinline__ void ldsm4(uint32_t* r, uint32_t addr) {
    asm volatile("ldmatrix.sync.aligned.m8n8.x4.shared.b16 {%0,%1,%2,%3}, [%4];"
        : "=r"(r[0]), "=r"(r[1]), "=r"(r[2]), "=r"(r[3]) : "r"(addr));
}

__device__ __forceinline__ void mma16816(float* c, const uint32_t* a,
                                         const uint32_t* b) {
    asm volatile(
        "mma.sync.aligned.m16n8k16.row.col.f32.f16.f16.f32 "
        "{%0,%1,%2,%3}, {%4,%5,%6,%7}, {%8,%9}, {%0,%1,%2,%3};"
        : "+f"(c[0]), "+f"(c[1]), "+f"(c[2]), "+f"(c[3])
        : "r"(a[0]), "r"(a[1]), "r"(a[2]), "r"(a[3]), "r"(b[0]), "r"(b[1]));
}

__device__ __forceinline__ void cp16(uint32_t dst, const void* src) {
    asm volatile("cp.async.cg.shared.global [%0], [%1], 16;"
        :: "r"(dst), "l"(src));
}
#define CP_COMMIT() asm volatile("cp.async.commit_group;" ::: "memory")
#define CP_WAIT(n)  asm volatile("cp.async.wait_group %0;" :: "n"(n) : "memory")

__device__ __forceinline__ uint32_t h2u(float a, float b) {
    __half2 h = __floats2half2_rn(a, b);
    return *(uint32_t*)&h;
}

// ---------------- small elementwise kernels ---------------------------------
__global__ void add_pos_kernel(const float* __restrict__ q,
                               const float* __restrict__ qa,
                               const float* __restrict__ pe,
                               float* __restrict__ x,
                               __half* __restrict__ xh,
                               __half* __restrict__ yh)
{
    int idx = blockIdx.x * 256 + threadIdx.x;
    int sd  = idx & (Ss*Dd - 1);
    float p = pe[sd];
    float xv = q[idx] + p;
    x[idx]  = xv;
    xh[idx] = __float2half(xv);
    yh[idx] = __float2half(qa[idx] + p);
}

// Convert all 5 weight matrices of one layer in a single launch.
#define NW1 (Dd*Dd)
#define NWF (FFf*Dd)
__global__ void wconv_all(const float* __restrict__ Wk,
                          const float* __restrict__ Wv,
                          const float* __restrict__ Wo,
                          const float* __restrict__ W1,
                          const float* __restrict__ W2,
                          __half* __restrict__ wk, __half* __restrict__ wv,
                          __half* __restrict__ wo, __half* __restrict__ w1,
                          __half* __restrict__ w2)
{
    int i = blockIdx.x * 256 + threadIdx.x;
    if (i < NW1)              wk[i] = __float2half(Wk[i]);
    else if (i < 2*NW1)       wv[i - NW1]   = __float2half(Wv[i - NW1]);
    else if (i < 3*NW1)       wo[i - 2*NW1] = __float2half(Wo[i - 2*NW1]);
    else if (i < 3*NW1 + NWF) w1[i - 3*NW1] = __float2half(W1[i - 3*NW1]);
    else                      w2[i - 3*NW1 - NWF] = __float2half(W2[i - 3*NW1 - NWF]);
}
#define WCONV_TOTAL (3*NW1 + 2*NWF)

// ============ fp16 GEMM: C = A * B^T (+bias)(+relu) =========================
// A: [M,K] fp16 row-major. B: [N,K] fp16 row-major. fp32 accumulate.
// CTA tile 128x128 (8 warps of 32x64), K staged 64 wide, 3-stage cp.async ring,
// one __syncthreads per stage, targets 2 CTAs/SM (16 warps) for latency hiding.
// outMode: 0 = fp32 Cf; 1 = fp16 Ch; 3 = fp16 Ch with vT scatter.
#define ROWB 144                    // 64 halves (128B) + 16B pad
#define ATILEB (128 * ROWB)         // 18432
#define BTILEB (128 * ROWB)         // 18432
#define STAGEB (ATILEB + BTILEB)    // 36864
#define NSTAGE 3
#define DSMEM_BYTES (NSTAGE * STAGEB)   // 110592

__device__ __forceinline__ void load_stage(
    int tid, uint32_t base,
    const __half* A, int lda, const __half* B, int ldb,
    int m0, int n0, int k0)
{
#pragma unroll
    for (int j = 0; j < 4; j++) {
        int c = tid + j * 256;              // 0..1023
        int row = c >> 3, c8 = c & 7;
        cp16(base + (uint32_t)(row * ROWB + c8 * 16),
             A + (long)(m0 + row) * lda + k0 + c8 * 8);
    }
#pragma unroll
    for (int j = 0; j < 4; j++) {
        int c = tid + j * 256;
        int row = c >> 3, c8 = c & 7;
        cp16(base + ATILEB + (uint32_t)(row * ROWB + c8 * 16),
             B + (long)(n0 + row) * ldb + k0 + c8 * 8);
    }
}

__global__ void __launch_bounds__(256, 2)
gemm_h(const __half* __restrict__ A, int lda,
       const __half* __restrict__ B, int ldb,
       const float* __restrict__ bias,
       float* __restrict__ Cf, __half* __restrict__ Ch,
       int ldc, int K, int relu, int outMode)
{
    extern __shared__ char dsm[];
    uint32_t sb = smem_u32(dsm);

    const int m0 = blockIdx.y * 128, n0 = blockIdx.x * 128;
    const int tid  = threadIdx.x;
    const int lane = tid & 31, wid = tid >> 5;
    const int mW = (wid & 3) * 32, nW = (wid >> 2) * 64;

    const uint32_t aRowOff = (uint32_t)((mW + (lane & 15)) * ROWB + (lane >> 4) * 16);
    const uint32_t bRowOff = (uint32_t)((nW + (lane & 7) + ((lane >> 4) * 8)) * ROWB
                                        + ((lane >> 3) & 1) * 16);

    const int nst = K >> 6;
    float acc[2][8][4] = {};

    load_stage(tid, sb, A, lda, B, ldb, m0, n0, 0);
    CP_COMMIT();
    if (nst > 1) load_stage(tid, sb + STAGEB, A, lda, B, ldb, m0, n0, 64);
    CP_COMMIT();

    int slot = 0;
    for (int s = 0; s < nst; s++) {
        CP_WAIT(1);
        __syncthreads();            // single barrier per stage
        uint32_t cur = sb + (uint32_t)slot * STAGEB;

        // prefetch stage s+2 into slot (s+2)%NSTAGE — safe: the barrier above
        // proves every warp finished reading that slot in stage s-1.
        if (s + 2 < nst) {
            int nslot = slot + 2; if (nslot >= NSTAGE) nslot -= NSTAGE;
            load_stage(tid, sb + (uint32_t)nslot * STAGEB,
                       A, lda, B, ldb, m0, n0, (s + 2) * 64);
        }
        CP_COMMIT();

#pragma unroll
        for (int kk = 0; kk < 4; kk++) {
            const uint32_t kb = (uint32_t)kk * 32;
            uint32_t a[2][4], b[4][4];
#pragma unroll
            for (int mt = 0; mt < 2; mt++)
                ldsm4(a[mt], cur + aRowOff + mt * (16 * ROWB) + kb);
#pragma unroll
            for (int nh = 0; nh < 4; nh++)
                ldsm4(b[nh], cur + ATILEB + bRowOff + nh * (16 * ROWB) + kb);
#pragma unroll
            for (int nh = 0; nh < 4; nh++)
#pragma unroll
                for (int hf = 0; hf < 2; hf++)
#pragma unroll
                    for (int mt = 0; mt < 2; mt++)
                        mma16816(acc[mt][nh*2+hf], a[mt], b[nh] + 2*hf);
        }
        slot++; if (slot == NSTAGE) slot = 0;
    }

    // ---- epilogue ----
    const int rIn = lane >> 2, cIn = (lane & 3) * 2;
#pragma unroll
    for (int mt = 0; mt < 2; mt++) {
#pragma unroll
        for (int nt = 0; nt < 8; nt++) {
            float* a4 = acc[mt][nt];
            int col = n0 + nW + nt*8 + cIn;
            long r0 = (long)m0 + mW + mt*16 + rIn;
            long r1 = r0 + 8;
            float v0 = a4[0], v1 = a4[1], v2 = a4[2], v3 = a4[3];
            if (bias) {
                float b0_ = bias[col], b1_ = bias[col+1];
                v0 += b0_; v1 += b1_; v2 += b0_; v3 += b1_;
            }
            if (relu) {
                v0 = fmaxf(v0,0.f); v1 = fmaxf(v1,0.f);
                v2 = fmaxf(v2,0.f); v3 = fmaxf(v3,0.f);
            }
            if (outMode == 0) {
                *(float2*)(Cf + r0*ldc + col) = make_float2(v0, v1);
                *(float2*)(Cf + r1*ldc + col) = make_float2(v2, v3);
            } else if (outMode == 1) {
                *(__half2*)(Ch + r0*ldc + col) = __floats2half2_rn(v0, v1);
                *(__half2*)(Ch + r1*ldc + col) = __floats2half2_rn(v2, v3);
            } else { // 3: vT scatter
                int b0i = (int)(r0 >> 10), s0 = (int)(r0 & 1023);
                int b1i = (int)(r1 >> 10), s1 = (int)(r1 & 1023);
                int h = col >> 7, dk = col & 127;
                Ch[((long)((b0i*Hh + h)*DKk + dk)     << 10) + s0] = __float2half(v0);
                Ch[((long)((b0i*Hh + h)*DKk + dk + 1) << 10) + s0] = __float2half(v1);
                Ch[((long)((b1i*Hh + h)*DKk + dk)     << 10) + s1] = __float2half(v2);
                Ch[((long)((b1i*Hh + h)*DKk + dk + 1) << 10) + s1] = __float2half(v3);
            }
        }
    }
}

// ============ fused flash attention (strict causal, row0 zeroed) ============
#define FROWB 272
#define FTILE (128 * FROWB)                 // 34816
#define FL_SMEM (5 * FTILE)                 // Q + 2xK + 2xV = 174080

__device__ __forceinline__ void fl_load(int tid, uint32_t dstK, uint32_t dstV,
                                        const __half* Kb, const __half* Vb,
                                        int s0)
{
#pragma unroll
    for (int j = 0; j < 8; j++) {
        int c = tid + j * 256;              // 0..2047
        int row = c >> 4, cc = c & 15;
        uint32_t off = (uint32_t)(row * FROWB + cc * 16);
        cp16(dstK + off, Kb + (long)(s0 + row) * Dd + cc * 8);
        cp16(dstV + off, Vb + (long)row * Ss + s0 + cc * 8);
    }
}

__global__ void __launch_bounds__(256, 1)
flash_attn(const __half* __restrict__ kh, const __half* __restrict__ vT,
           __half* __restrict__ t1h)
{
    extern __shared__ char dsm[];
    uint32_t sb = smem_u32(dsm);
    uint32_t sQ = sb, sK = sb + FTILE, sV = sb + 3 * FTILE;

    const int q0 = blockIdx.x * 128;
    const int bh = blockIdx.y;
    const int b = bh >> 3, h = bh & 7;
    const __half* Kbase = kh + ((long)b * Ss) * Dd + h * DKk;
    const __half* Vbase = vT + ((long)bh * DKk) * Ss;

    const int tid = threadIdx.x, lane = tid & 31, w = tid >> 5;
    const float isd = 0.08838834764831845f;

#pragma unroll
    for (int j = 0; j < 8; j++) {
        int c = tid + j * 256;
        int row = c >> 4, cc = c & 15;
        cp16(sQ + (uint32_t)(row * FROWB + cc * 16),
             Kbase + (long)(q0 + row) * Dd + cc * 8);
    }
    CP_COMMIT();
    fl_load(tid, sK, sV, Kbase, Vbase, 0);
    CP_COMMIT();

    CP_WAIT(1);
    __syncthreads();

    uint32_t qf[8][4];
    const uint32_t qAddr = sQ + (uint32_t)((w * 16 + (lane & 15)) * FROWB
                                           + (lane >> 4) * 16);
#pragma unroll
    for (int kk = 0; kk < 8; kk++) ldsm4(qf[kk], qAddr + kk * 32);

    float o[16][4] = {};
    float mS[2] = {-1e30f, -1e30f};
    float lS[2] = {0.f, 0.f};

    const uint32_t bOff = (uint32_t)(((lane & 7) + ((lane >> 4) * 8)) * FROWB
                                     + ((lane >> 3) & 1) * 16);
    const int nkb = q0 / 128 + 1;

    for (int kb = 0; kb < nkb; kb++) {
        if (kb + 1 < nkb)
            fl_load(tid, sK + (uint32_t)((kb + 1) & 1) * FTILE,
                    sV + (uint32_t)((kb + 1) & 1) * FTILE,
                    Kbase, Vbase, (kb + 1) * 128);
        CP_COMMIT();
        CP_WAIT(1);
        __syncthreads();
        uint32_t curK = sK + (uint32_t)(kb & 1) * FTILE;
        uint32_t curV = sV + (uint32_t)(kb & 1) * FTILE;

        float s[16][4] = {};
#pragma unroll
        for (int kk = 0; kk < 8; kk++) {
            uint32_t bf[8][4];
#pragma unroll
            for (int p = 0; p < 8; p++)
                ldsm4(bf[p], curK + bOff + p * (16 * FROWB) + kk * 32);
#pragma unroll
            for (int p = 0; p < 8; p++) {
                mma16816(s[2*p],   qf[kk], bf[p]);
                mma16816(s[2*p+1], qf[kk], bf[p] + 2);
            }
        }
#pragma unroll
        for (int nt = 0; nt < 16; nt++) {
            s[nt][0] *= isd; s[nt][1] *= isd; s[nt][2] *= isd; s[nt][3] *= isd;
        }

        if (kb == nkb - 1) {
            int rA = q0 + w * 16 + (lane >> 2);
            int rB = rA + 8;
            int cb = kb * 128 + (lane & 3) * 2;
#pragma unroll
            for (int nt = 0; nt < 16; nt++) {
                int c0 = cb + nt * 8, c1 = c0 + 1;
                if (c0 >= rA) s[nt][0] = -1e30f;
                if (c1 >= rA) s[nt][1] = -1e30f;
                if (c0 >= rB) s[nt][2] = -1e30f;
                if (c1 >= rB) s[nt][3] = -1e30f;
            }
        }

        float rAm = -1e30f, rBm = -1e30f;
#pragma unroll
        for (int nt = 0; nt < 16; nt++) {
            rAm = fmaxf(rAm, fmaxf(s[nt][0], s[nt][1]));
            rBm = fmaxf(rBm, fmaxf(s[nt][2], s[nt][3]));
        }
        rAm = fmaxf(rAm, __shfl_xor_sync(0xFFFFFFFFu, rAm, 1));
        rAm = fmaxf(rAm, __shfl_xor_sync(0xFFFFFFFFu, rAm, 2));
        rBm = fmaxf(rBm, __shfl_xor_sync(0xFFFFFFFFu, rBm, 1));
        rBm = fmaxf(rBm, __shfl_xor_sync(0xFFFFFFFFu, rBm, 2));

        float mA = fmaxf(mS[0], rAm), mB = fmaxf(mS[1], rBm);
        float aA = __expf(mS[0] - mA), aB = __expf(mS[1] - mB);
        mS[0] = mA; mS[1] = mB;

        float sumA = 0.f, sumB = 0.f;
        uint32_t pf[8][4];
#pragma unroll
        for (int j = 0; j < 8; j++) {
            float e0 = __expf(s[2*j][0]   - mA), e1 = __expf(s[2*j][1]   - mA);
            float e2 = __expf(s[2*j][2]   - mB), e3 = __expf(s[2*j][3]   - mB);
            float f0 = __expf(s[2*j+1][0] - mA), f1 = __expf(s[2*j+1][1] - mA);
            float f2 = __expf(s[2*j+1][2] - mB), f3 = __expf(s[2*j+1][3] - mB);
            sumA += e0 + e1 + f0 + f1;
            sumB += e2 + e3 + f2 + f3;
            pf[j][0] = h2u(e0, e1); pf[j][1] = h2u(e2, e3);
            pf[j][2] = h2u(f0, f1); pf[j][3] = h2u(f2, f3);
        }
        sumA += __shfl_xor_sync(0xFFFFFFFFu, sumA, 1);
        sumA += __shfl_xor_sync(0xFFFFFFFFu, sumA, 2);
        sumB += __shfl_xor_sync(0xFFFFFFFFu, sumB, 1);
        sumB += __shfl_xor_sync(0xFFFFFFFFu, sumB, 2);
        lS[0] = lS[0] * aA + sumA;
        lS[1] = lS[1] * aB + sumB;

#pragma unroll
        for (int nt = 0; nt < 16; nt++) {
            o[nt][0] *= aA; o[nt][1] *= aA; o[nt][2] *= aB; o[nt][3] *= aB;
        }

#pragma unroll
        for (int j = 0; j < 8; j++) {
            uint32_t vf[8][4];
#pragma unroll
            for (int p = 0; p < 8; p++)
                ldsm4(vf[p], curV + bOff + p * (16 * FROWB) + j * 32);
#pragma unroll
            for (int p = 0; p < 8; p++) {
                mma16816(o[2*p],   pf[j], vf[p]);
                mma16816(o[2*p+1], pf[j], vf[p] + 2);
            }
        }
        __syncthreads();
    }

    int rowA = q0 + w * 16 + (lane >> 2);
    int rowB = rowA + 8;
    float invA = (rowA == 0) ? 0.f : 1.f / lS[0];
    float invB = 1.f / lS[1];
    __half* oA = t1h + ((long)b * Ss + rowA) * Dd + h * DKk + (lane & 3) * 2;
    __half* oB = t1h + ((long)b * Ss + rowB) * Dd + h * DKk + (lane & 3) * 2;
#pragma unroll
    for (int nt = 0; nt < 16; nt++) {
        *(__half2*)(oA + nt * 8) = __floats2half2_rn(o[nt][0]*invA, o[nt][1]*invA);
        *(__half2*)(oB + nt * 8) = __floats2half2_rn(o[nt][2]*invB, o[nt][3]*invB);
    }
}

// ---------------- residual add + LayerNorm (fp32 out + optional fp16) -------
__global__ void ln_res(const float* __restrict__ x, const float* __restrict__ t,
                       const float* __restrict__ g, const float* __restrict__ b,
                       float* __restrict__ out, __half* __restrict__ outh)
{
    __shared__ float red[256];
    long row = blockIdx.x;
    int tid = threadIdx.x;
    const float* xp = x + row * Dd;
    const float* tp = t + row * Dd;

    float v[4];
    float s = 0.f;
#pragma unroll
    for (int q = 0; q < 4; q++) {
        int c = tid + q * 256;
        v[q] = xp[c] + tp[c];
        s += v[q];
    }
    red[tid] = s; __syncthreads();
    for (int off = 128; off > 0; off >>= 1) {
        if (tid < off) red[tid] += red[tid + off];
        __syncthreads();
    }
    float mean = red[0] * (1.f / Dd);
    __syncthreads();

    float s2 = 0.f;
#pragma unroll
    for (int q = 0; q < 4; q++) {
        float d = v[q] - mean;
        s2 += d * d;
    }
    red[tid] = s2; __syncthreads();
    for (int off = 128; off > 0; off >>= 1) {
        if (tid < off) red[tid] += red[tid + off];
        __syncthreads();
    }
    float inv = rsqrtf(red[0] * (1.f / Dd) + 1e-5f);

#pragma unroll
    for (int q = 0; q < 4; q++) {
        int c = tid + q * 256;
        float val = (v[q] - mean) * inv * g[c] + b[c];
        out[row * Dd + c] = val;
        if (outh) outh[row * Dd + c] = __float2half(val);
    }
}

// ---------------- driver ----------------------------------------------------
extern "C" void kernel_launch(void* const* d_in, const int* in_sizes, int n_in,
                              void* d_out, int out_size)
{
    const float* q_embed = (const float*)d_in[0];
    const float* qa_embed= (const float*)d_in[1];
    const float* pos     = (const float*)d_in[2];
    const float* Wk  = (const float*)d_in[3];
    const float* bk  = (const float*)d_in[4];
    const float* Wv  = (const float*)d_in[5];
    const float* bv  = (const float*)d_in[6];
    const float* Wo  = (const float*)d_in[7];
    const float* bo  = (const float*)d_in[8];
    const float* ln1g= (const float*)d_in[9];
    const float* ln1b= (const float*)d_in[10];
    const float* W1  = (const float*)d_in[11];
    const float* b1  = (const float*)d_in[12];
    const float* W2  = (const float*)d_in[13];
    const float* b2  = (const float*)d_in[14];
    const float* ln2g= (const float*)d_in[15];
    const float* ln2b= (const float*)d_in[16];
    float* out = (float*)d_out;

    float *x, *t2;
    __half *xh, *yh, *kh, *vh, *t1h, *ffh;
    __half *wk, *wv, *wo, *w1, *w2;
    cudaGetSymbolAddress((void**)&x,   g_x);
    cudaGetSymbolAddress((void**)&t2,  g_t2);
    cudaGetSymbolAddress((void**)&xh,  g_xh);
    cudaGetSymbolAddress((void**)&yh,  g_yh);
    cudaGetSymbolAddress((void**)&kh,  g_kh);
    cudaGetSymbolAddress((void**)&vh,  g_vh);
    cudaGetSymbolAddress((void**)&t1h, g_t1h);
    cudaGetSymbolAddress((void**)&ffh, g_ffh);
    cudaGetSymbolAddress((void**)&wk,  g_wk);
    cudaGetSymbolAddress((void**)&wv,  g_wv);
    cudaGetSymbolAddress((void**)&wo,  g_wo);
    cudaGetSymbolAddress((void**)&w1,  g_w1);
    cudaGetSymbolAddress((void**)&w2,  g_w2);

    cudaFuncSetAttribute(gemm_h, cudaFuncAttributeMaxDynamicSharedMemorySize,
                         DSMEM_BYTES);
    cudaFuncSetAttribute(flash_attn, cudaFuncAttributeMaxDynamicSharedMemorySize,
                         FL_SMEM);

    add_pos_kernel<<<(Bb*Ss*Dd)/256, 256>>>(q_embed, qa_embed, pos, x, xh, yh);

    for (int l = 0; l < Ll; l++) {
        const float* bkl_ = bk + (long)l*Dd;
        const float* bvl_ = bv + (long)l*Dd;
        const float* bol_ = bo + (long)l*Dd;
        const float* b1l_ = b1 + (long)l*FFf;
        const float* b2l_ = b2 + (long)l*Dd;

        wconv_all<<<(WCONV_TOTAL + 255)/256, 256>>>(
            Wk + (long)l*Dd*Dd, Wv + (long)l*Dd*Dd, Wo + (long)l*Dd*Dd,
            W1 + (long)l*FFf*Dd, W2 + (long)l*Dd*FFf,
            wk, wv, wo, w1, w2);

        dim3 gP (Dd/128,  (Bb*Ss)/128);
        dim3 gF1(FFf/128, (Bb*Ss)/128);
        dim3 gF2(Dd/128,  (Bb*Ss)/128);
        dim3 gFA(Ss/128,  Bb*Hh);

        // K = x @ Wk^T + bk  -> fp16 (q == k)
        gemm_h<<<gP, 256, DSMEM_BYTES>>>(xh, Dd, wk, Dd, bkl_,
            nullptr, kh, Dd, Dd, 0, 1);
        // vT = (y @ Wv^T + bv)^T scatter -> fp16
        gemm_h<<<gP, 256, DSMEM_BYTES>>>(yh, Dd, wv, Dd, bvl_,
            nullptr, vh, Dd, Dd, 0, 3);
        // fused attention: scores + masked softmax + P@V -> t1h
        flash_attn<<<gFA, 256, FL_SMEM>>>(kh, vh, t1h);
        // t2 = t1 @ Wo^T + bo -> fp32      (launch #6 overall: ncu target)
        gemm_h<<<gP, 256, DSMEM_BYTES>>>(t1h, Dd, wo, Dd, bol_,
            t2, nullptr, Dd, Dd, 0, 0);
        // x = LN(x + t2) -> fp32 + fp16
        ln_res<<<Bb*Ss, 256>>>(x, t2, ln1g + (long)l*Dd, ln1b + (long)l*Dd, x, xh);
        // ff = relu(x @ W1^T + b1) -> fp16
        gemm_h<<<gF1, 256, DSMEM_BYTES>>>(xh, Dd, w1, Dd, b1l_,
            nullptr, ffh, FFf, Dd, 1, 1);
        // t2 = ff @ W2^T + b2 -> fp32
        gemm_h<<<gF2, 256, DSMEM_BYTES>>>(ffh, FFf, w2, FFf, b2l_,
            t2, nullptr, Dd, FFf, 0, 0);
        // x = LN(x + t2); final layer -> d_out (fp32 only)
        float* xout = (l == Ll - 1) ? out : x;
        __half* xhout = (l == Ll - 1) ? nullptr : xh;
        ln_res<<<Bb*Ss, 256>>>(x, t2, ln2g + (long)l*Dd, ln2b + (long)l*Dd,
                               xout, xhout);
    }
}

// round 9
// speedup vs baseline: 8.3942x; 1.0082x over previous
#include <cuda_runtime.h>
#include <cuda_fp16.h>
#include <math.h>
#include <stdint.h>

// Problem constants
#define Bb 8
#define Ss 1024
#define Dd 1024
#define Hh 8
#define DKk 128
#define FFf 4096
#define Ll 2

// ---------------- scratch (device globals; no allocation allowed) ----------
__device__ float  g_x [Bb*Ss*Dd];                 // fp32 activation (residual)
__device__ __half g_t2h[Bb*Ss*Dd];                // fp16 branch output
__device__ __half g_xh [Bb*Ss*Dd];
__device__ __half g_yh [Bb*Ss*Dd];
__device__ __half g_kh [Bb*Ss*Dd];
__device__ __half g_vh [Bb*Ss*Dd];                // V row-major [b,s,h*dk]
__device__ __half g_t1h[Bb*Ss*Dd];
__device__ __half g_ffh[Bb*Ss*FFf];
// fp16 weights (converted per layer)
__device__ __half g_wk[Dd*Dd];
__device__ __half g_wv[Dd*Dd];
__device__ __half g_wo[Dd*Dd];
__device__ __half g_w1[FFf*Dd];
__device__ __half g_w2[Dd*FFf];

// ======================= helpers ============================================
__device__ __forceinline__ uint32_t smem_u32(const void* p) {
    uint32_t a;
    asm("{ .reg .u64 t; cvta.to.shared.u64 t, %1; cvt.u32.u64 %0, t; }"
        : "=r"(a) : "l"(p));
    return a;
}

__device__ __forceinline__ void ldsm4(uint32_t* r, uint32_t addr) {
    asm volatile("ldmatrix.sync.aligned.m8n8.x4.shared.b16 {%0,%1,%2,%3}, [%4];"
        : "=r"(r[0]), "=r"(r[1]), "=r"(r[2]), "=r"(r[3]) : "r"(addr));
}

__device__ __forceinline__ void ldsm4t(uint32_t* r, uint32_t addr) {
    asm volatile("ldmatrix.sync.aligned.m8n8.x4.trans.shared.b16 {%0,%1,%2,%3}, [%4];"
        : "=r"(r[0]), "=r"(r[1]), "=r"(r[2]), "=r"(r[3]) : "r"(addr));
}

__device__ __forceinline__ void mma16816(float* c, const uint32_t* a,
                                         const uint32_t* b) {
    asm volatile(
        "mma.sync.aligned.m16n8k16.row.col.f32.f16.f16.f32 "
        "{%0,%1,%2,%3}, {%4,%5,%6,%7}, {%8,%9}, {%0,%1,%2,%3};"
        : "+f"(c[0]), "+f"(c[1]), "+f"(c[2]), "+f"(c[3])
        : "r"(a[0]), "r"(a[1]), "r"(a[2]), "r"(a[3]), "r"(b[0]), "r"(b[1]));
}

__device__ __forceinline__ void cp16(uint32_t dst, const void* src) {
    asm volatile("cp.async.cg.shared.global [%0], [%1], 16;"
        :: "r"(dst), "l"(src));
}
#define CP_COMMIT() asm volatile("cp.async.commit_group;" ::: "memory")
#define CP_WAIT(n)  asm volatile("cp.async.wait_group %0;" :: "n"(n) : "memory")

__device__ __forceinline__ uint32_t h2u(float a, float b) {
    __half2 h = __floats2half2_rn(a, b);
    return *(uint32_t*)&h;
}

// ---------------- small elementwise kernels ---------------------------------
__global__ void add_pos_kernel(const float* __restrict__ q,
                               const float* __restrict__ qa,
                               const float* __restrict__ pe,
                               float* __restrict__ x,
                               __half* __restrict__ xh,
                               __half* __restrict__ yh)
{
    int idx = blockIdx.x * 256 + threadIdx.x;
    int sd  = idx & (Ss*Dd - 1);
    float p = pe[sd];
    float xv = q[idx] + p;
    x[idx]  = xv;
    xh[idx] = __float2half(xv);
    yh[idx] = __float2half(qa[idx] + p);
}

// Convert all 5 weight matrices of one layer in a single launch.
#define NW1 (Dd*Dd)
#define NWF (FFf*Dd)
__global__ void wconv_all(const float* __restrict__ Wk,
                          const float* __restrict__ Wv,
                          const float* __restrict__ Wo,
                          const float* __restrict__ W1,
                          const float* __restrict__ W2,
                          __half* __restrict__ wk, __half* __restrict__ wv,
                          __half* __restrict__ wo, __half* __restrict__ w1,
                          __half* __restrict__ w2)
{
    int i = blockIdx.x * 256 + threadIdx.x;
    if (i < NW1)              wk[i] = __float2half(Wk[i]);
    else if (i < 2*NW1)       wv[i - NW1]   = __float2half(Wv[i - NW1]);
    else if (i < 3*NW1)       wo[i - 2*NW1] = __float2half(Wo[i - 2*NW1]);
    else if (i < 3*NW1 + NWF) w1[i - 3*NW1] = __float2half(W1[i - 3*NW1]);
    else                      w2[i - 3*NW1 - NWF] = __float2half(W2[i - 3*NW1 - NWF]);
}
#define WCONV_TOTAL (3*NW1 + 2*NWF)

// ============ fp16 GEMM: C = A * B^T (+bias)(+relu) =========================
// A: [M,K] fp16 row-major. B: [N,K] fp16 row-major. fp32 accumulate.
// CTA tile 128x128 (8 warps of 32x64), K staged 64 wide, 3-stage cp.async ring,
// one __syncthreads per stage, 2 CTAs/SM.  relu flag; fp16 output only.
#define ROWB 144                    // 64 halves (128B) + 16B pad
#define ATILEB (128 * ROWB)         // 18432
#define BTILEB (128 * ROWB)         // 18432
#define STAGEB (ATILEB + BTILEB)    // 36864
#define NSTAGE 3
#define DSMEM_BYTES (NSTAGE * STAGEB)   // 110592

__device__ __forceinline__ void load_stage(
    int tid, uint32_t base,
    const __half* A, int lda, const __half* B, int ldb,
    int m0, int n0, int k0)
{
#pragma unroll
    for (int j = 0; j < 4; j++) {
        int c = tid + j * 256;              // 0..1023
        int row = c >> 3, c8 = c & 7;
        cp16(base + (uint32_t)(row * ROWB + c8 * 16),
             A + (long)(m0 + row) * lda + k0 + c8 * 8);
    }
#pragma unroll
    for (int j = 0; j < 4; j++) {
        int c = tid + j * 256;
        int row = c >> 3, c8 = c & 7;
        cp16(base + ATILEB + (uint32_t)(row * ROWB + c8 * 16),
             B + (long)(n0 + row) * ldb + k0 + c8 * 8);
    }
}

__global__ void __launch_bounds__(256, 2)
gemm_h(const __half* __restrict__ A, int lda,
       const __half* __restrict__ B, int ldb,
       const float* __restrict__ bias,
       __half* __restrict__ Ch,
       int ldc, int K, int relu)
{
    extern __shared__ char dsm[];
    uint32_t sb = smem_u32(dsm);

    const int m0 = blockIdx.y * 128, n0 = blockIdx.x * 128;
    const int tid  = threadIdx.x;
    const int lane = tid & 31, wid = tid >> 5;
    const int mW = (wid & 3) * 32, nW = (wid >> 2) * 64;

    const uint32_t aRowOff = (uint32_t)((mW + (lane & 15)) * ROWB + (lane >> 4) * 16);
    const uint32_t bRowOff = (uint32_t)((nW + (lane & 7) + ((lane >> 4) * 8)) * ROWB
                                        + ((lane >> 3) & 1) * 16);

    const int nst = K >> 6;
    float acc[2][8][4] = {};

    load_stage(tid, sb, A, lda, B, ldb, m0, n0, 0);
    CP_COMMIT();
    if (nst > 1) load_stage(tid, sb + STAGEB, A, lda, B, ldb, m0, n0, 64);
    CP_COMMIT();

    int slot = 0;
    for (int s = 0; s < nst; s++) {
        CP_WAIT(1);
        __syncthreads();            // single barrier per stage
        uint32_t cur = sb + (uint32_t)slot * STAGEB;

        if (s + 2 < nst) {
            int nslot = slot + 2; if (nslot >= NSTAGE) nslot -= NSTAGE;
            load_stage(tid, sb + (uint32_t)nslot * STAGEB,
                       A, lda, B, ldb, m0, n0, (s + 2) * 64);
        }
        CP_COMMIT();

#pragma unroll
        for (int kk = 0; kk < 4; kk++) {
            const uint32_t kb = (uint32_t)kk * 32;
            uint32_t a[2][4], b[4][4];
#pragma unroll
            for (int mt = 0; mt < 2; mt++)
                ldsm4(a[mt], cur + aRowOff + mt * (16 * ROWB) + kb);
#pragma unroll
            for (int nh = 0; nh < 4; nh++)
                ldsm4(b[nh], cur + ATILEB + bRowOff + nh * (16 * ROWB) + kb);
#pragma unroll
            for (int nh = 0; nh < 4; nh++)
#pragma unroll
                for (int hf = 0; hf < 2; hf++)
#pragma unroll
                    for (int mt = 0; mt < 2; mt++)
                        mma16816(acc[mt][nh*2+hf], a[mt], b[nh] + 2*hf);
        }
        slot++; if (slot == NSTAGE) slot = 0;
    }

    // ---- epilogue: fp16 output ----
    const int rIn = lane >> 2, cIn = (lane & 3) * 2;
#pragma unroll
    for (int mt = 0; mt < 2; mt++) {
#pragma unroll
        for (int nt = 0; nt < 8; nt++) {
            float* a4 = acc[mt][nt];
            int col = n0 + nW + nt*8 + cIn;
            long r0 = (long)m0 + mW + mt*16 + rIn;
            long r1 = r0 + 8;
            float v0 = a4[0], v1 = a4[1], v2 = a4[2], v3 = a4[3];
            if (bias) {
                float b0_ = bias[col], b1_ = bias[col+1];
                v0 += b0_; v1 += b1_; v2 += b0_; v3 += b1_;
            }
            if (relu) {
                v0 = fmaxf(v0,0.f); v1 = fmaxf(v1,0.f);
                v2 = fmaxf(v2,0.f); v3 = fmaxf(v3,0.f);
            }
            *(__half2*)(Ch + r0*ldc + col) = __floats2half2_rn(v0, v1);
            *(__half2*)(Ch + r1*ldc + col) = __floats2half2_rn(v2, v3);
        }
    }
}

// ============ fused flash attention (strict causal, row0 zeroed) ============
// Per CTA: one (b,h) and one 128-row q-block. 8 warps, each owns 16 q-rows.
// Q and K from kh (kq_same), both [b,s,h*dk].  V from vh, SAME row-major layout;
// V fragments come via ldmatrix.trans (no pre-transposed vT buffer needed).
#define FROWB 272
#define FTILE (128 * FROWB)                 // 34816
#define FL_SMEM (5 * FTILE)                 // Q + 2xK + 2xV = 174080

__device__ __forceinline__ void fl_load(int tid, uint32_t dstK, uint32_t dstV,
                                        const __half* Kb, const __half* Vb,
                                        int s0)
{
#pragma unroll
    for (int j = 0; j < 8; j++) {
        int c = tid + j * 256;              // 0..2047
        int row = c >> 4, cc = c & 15;
        uint32_t off = (uint32_t)(row * FROWB + cc * 16);
        cp16(dstK + off, Kb + (long)(s0 + row) * Dd + cc * 8);
        cp16(dstV + off, Vb + (long)(s0 + row) * Dd + cc * 8);
    }
}

__global__ void __launch_bounds__(256, 1)
flash_attn(const __half* __restrict__ kh, const __half* __restrict__ vh,
           __half* __restrict__ t1h)
{
    extern __shared__ char dsm[];
    uint32_t sb = smem_u32(dsm);
    uint32_t sQ = sb, sK = sb + FTILE, sV = sb + 3 * FTILE;

    const int q0 = blockIdx.x * 128;
    const int bh = blockIdx.y;
    const int b = bh >> 3, h = bh & 7;
    const __half* Kbase = kh + ((long)b * Ss) * Dd + h * DKk;
    const __half* Vbase = vh + ((long)b * Ss) * Dd + h * DKk;

    const int tid = threadIdx.x, lane = tid & 31, w = tid >> 5;
    const float isd = 0.08838834764831845f;

#pragma unroll
    for (int j = 0; j < 8; j++) {
        int c = tid + j * 256;
        int row = c >> 4, cc = c & 15;
        cp16(sQ + (uint32_t)(row * FROWB + cc * 16),
             Kbase + (long)(q0 + row) * Dd + cc * 8);
    }
    CP_COMMIT();
    fl_load(tid, sK, sV, Kbase, Vbase, 0);
    CP_COMMIT();

    CP_WAIT(1);
    __syncthreads();

    uint32_t qf[8][4];
    const uint32_t qAddr = sQ + (uint32_t)((w * 16 + (lane & 15)) * FROWB
                                           + (lane >> 4) * 16);
#pragma unroll
    for (int kk = 0; kk < 8; kk++) ldsm4(qf[kk], qAddr + kk * 32);

    float o[16][4] = {};
    float mS[2] = {-1e30f, -1e30f};
    float lS[2] = {0.f, 0.f};

    // K fragments (non-trans): rows = s, 16B col groups = dk
    const uint32_t bOff = (uint32_t)(((lane & 7) + ((lane >> 4) * 8)) * FROWB
                                     + ((lane >> 3) & 1) * 16);
    // V fragments (trans): rows = s (lane&15), col halves = dk
    const uint32_t vOff = (uint32_t)((lane & 15) * FROWB + (lane >> 4) * 16);
    const int nkb = q0 / 128 + 1;

    for (int kb = 0; kb < nkb; kb++) {
        if (kb + 1 < nkb)
            fl_load(tid, sK + (uint32_t)((kb + 1) & 1) * FTILE,
                    sV + (uint32_t)((kb + 1) & 1) * FTILE,
                    Kbase, Vbase, (kb + 1) * 128);
        CP_COMMIT();
        CP_WAIT(1);
        __syncthreads();
        uint32_t curK = sK + (uint32_t)(kb & 1) * FTILE;
        uint32_t curV = sV + (uint32_t)(kb & 1) * FTILE;

        // ---- S = Q @ Kblk^T ----
        float s[16][4] = {};
#pragma unroll
        for (int kk = 0; kk < 8; kk++) {
            uint32_t bf[8][4];
#pragma unroll
            for (int p = 0; p < 8; p++)
                ldsm4(bf[p], curK + bOff + p * (16 * FROWB) + kk * 32);
#pragma unroll
            for (int p = 0; p < 8; p++) {
                mma16816(s[2*p],   qf[kk], bf[p]);
                mma16816(s[2*p+1], qf[kk], bf[p] + 2);
            }
        }
#pragma unroll
        for (int nt = 0; nt < 16; nt++) {
            s[nt][0] *= isd; s[nt][1] *= isd; s[nt][2] *= isd; s[nt][3] *= isd;
        }

        if (kb == nkb - 1) {
            int rA = q0 + w * 16 + (lane >> 2);
            int rB = rA + 8;
            int cb = kb * 128 + (lane & 3) * 2;
#pragma unroll
            for (int nt = 0; nt < 16; nt++) {
                int c0 = cb + nt * 8, c1 = c0 + 1;
                if (c0 >= rA) s[nt][0] = -1e30f;
                if (c1 >= rA) s[nt][1] = -1e30f;
                if (c0 >= rB) s[nt][2] = -1e30f;
                if (c1 >= rB) s[nt][3] = -1e30f;
            }
        }

        // ---- online softmax ----
        float rAm = -1e30f, rBm = -1e30f;
#pragma unroll
        for (int nt = 0; nt < 16; nt++) {
            rAm = fmaxf(rAm, fmaxf(s[nt][0], s[nt][1]));
            rBm = fmaxf(rBm, fmaxf(s[nt][2], s[nt][3]));
        }
        rAm = fmaxf(rAm, __shfl_xor_sync(0xFFFFFFFFu, rAm, 1));
        rAm = fmaxf(rAm, __shfl_xor_sync(0xFFFFFFFFu, rAm, 2));
        rBm = fmaxf(rBm, __shfl_xor_sync(0xFFFFFFFFu, rBm, 1));
        rBm = fmaxf(rBm, __shfl_xor_sync(0xFFFFFFFFu, rBm, 2));

        float mA = fmaxf(mS[0], rAm), mB = fmaxf(mS[1], rBm);
        float aA = __expf(mS[0] - mA), aB = __expf(mS[1] - mB);
        mS[0] = mA; mS[1] = mB;

        float sumA = 0.f, sumB = 0.f;
        uint32_t pf[8][4];
#pragma unroll
        for (int j = 0; j < 8; j++) {
            float e0 = __expf(s[2*j][0]   - mA), e1 = __expf(s[2*j][1]   - mA);
            float e2 = __expf(s[2*j][2]   - mB), e3 = __expf(s[2*j][3]   - mB);
            float f0 = __expf(s[2*j+1][0] - mA), f1 = __expf(s[2*j+1][1] - mA);
            float f2 = __expf(s[2*j+1][2] - mB), f3 = __expf(s[2*j+1][3] - mB);
            sumA += e0 + e1 + f0 + f1;
            sumB += e2 + e3 + f2 + f3;
            pf[j][0] = h2u(e0, e1); pf[j][1] = h2u(e2, e3);
            pf[j][2] = h2u(f0, f1); pf[j][3] = h2u(f2, f3);
        }
        sumA += __shfl_xor_sync(0xFFFFFFFFu, sumA, 1);
        sumA += __shfl_xor_sync(0xFFFFFFFFu, sumA, 2);
        sumB += __shfl_xor_sync(0xFFFFFFFFu, sumB, 1);
        sumB += __shfl_xor_sync(0xFFFFFFFFu, sumB, 2);
        lS[0] = lS[0] * aA + sumA;
        lS[1] = lS[1] * aB + sumB;

#pragma unroll
        for (int nt = 0; nt < 16; nt++) {
            o[nt][0] *= aA; o[nt][1] *= aA; o[nt][2] *= aB; o[nt][3] *= aB;
        }

        // ---- O += P @ Vblk  (V row-major, fragments via trans ldsm) ----
#pragma unroll
        for (int j = 0; j < 8; j++) {           // j = s16 chunk (k of this mma)
            uint32_t vf[8][4];
#pragma unroll
            for (int p = 0; p < 8; p++)         // p = dk16 chunk (n of this mma)
                ldsm4t(vf[p], curV + vOff + j * (16 * FROWB) + p * 32);
#pragma unroll
            for (int p = 0; p < 8; p++) {
                mma16816(o[2*p],   pf[j], vf[p]);
                mma16816(o[2*p+1], pf[j], vf[p] + 2);
            }
        }
        __syncthreads();
    }

    int rowA = q0 + w * 16 + (lane >> 2);
    int rowB = rowA + 8;
    float invA = (rowA == 0) ? 0.f : 1.f / lS[0];
    float invB = 1.f / lS[1];
    __half* oA = t1h + ((long)b * Ss + rowA) * Dd + h * DKk + (lane & 3) * 2;
    __half* oB = t1h + ((long)b * Ss + rowB) * Dd + h * DKk + (lane & 3) * 2;
#pragma unroll
    for (int nt = 0; nt < 16; nt++) {
        *(__half2*)(oA + nt * 8) = __floats2half2_rn(o[nt][0]*invA, o[nt][1]*invA);
        *(__half2*)(oB + nt * 8) = __floats2half2_rn(o[nt][2]*invB, o[nt][3]*invB);
    }
}

// ---------------- residual add + LayerNorm (t input fp16) -------------------
__global__ void ln_res(const float* __restrict__ x, const __half* __restrict__ t,
                       const float* __restrict__ g, const float* __restrict__ b,
                       float* __restrict__ out, __half* __restrict__ outh)
{
    __shared__ float red[256];
    long row = blockIdx.x;
    int tid = threadIdx.x;
    const float*  xp = x + row * Dd;
    const __half* tp = t + row * Dd;

    float v[4];
    float s = 0.f;
#pragma unroll
    for (int q = 0; q < 4; q++) {
        int c = tid + q * 256;
        v[q] = xp[c] + __half2float(tp[c]);
        s += v[q];
    }
    red[tid] = s; __syncthreads();
    for (int off = 128; off > 0; off >>= 1) {
        if (tid < off) red[tid] += red[tid + off];
        __syncthreads();
    }
    float mean = red[0] * (1.f / Dd);
    __syncthreads();

    float s2 = 0.f;
#pragma unroll
    for (int q = 0; q < 4; q++) {
        float d = v[q] - mean;
        s2 += d * d;
    }
    red[tid] = s2; __syncthreads();
    for (int off = 128; off > 0; off >>= 1) {
        if (tid < off) red[tid] += red[tid + off];
        __syncthreads();
    }
    float inv = rsqrtf(red[0] * (1.f / Dd) + 1e-5f);

#pragma unroll
    for (int q = 0; q < 4; q++) {
        int c = tid + q * 256;
        float val = (v[q] - mean) * inv * g[c] + b[c];
        out[row * Dd + c] = val;
        if (outh) outh[row * Dd + c] = __float2half(val);
    }
}

// ---------------- driver ----------------------------------------------------
extern "C" void kernel_launch(void* const* d_in, const int* in_sizes, int n_in,
                              void* d_out, int out_size)
{
    const float* q_embed = (const float*)d_in[0];
    const float* qa_embed= (const float*)d_in[1];
    const float* pos     = (const float*)d_in[2];
    const float* Wk  = (const float*)d_in[3];
    const float* bk  = (const float*)d_in[4];
    const float* Wv  = (const float*)d_in[5];
    const float* bv  = (const float*)d_in[6];
    const float* Wo  = (const float*)d_in[7];
    const float* bo  = (const float*)d_in[8];
    const float* ln1g= (const float*)d_in[9];
    const float* ln1b= (const float*)d_in[10];
    const float* W1  = (const float*)d_in[11];
    const float* b1  = (const float*)d_in[12];
    const float* W2  = (const float*)d_in[13];
    const float* b2  = (const float*)d_in[14];
    const float* ln2g= (const float*)d_in[15];
    const float* ln2b= (const float*)d_in[16];
    float* out = (float*)d_out;

    float *x;
    __half *t2h, *xh, *yh, *kh, *vh, *t1h, *ffh;
    __half *wk, *wv, *wo, *w1, *w2;
    cudaGetSymbolAddress((void**)&x,   g_x);
    cudaGetSymbolAddress((void**)&t2h, g_t2h);
    cudaGetSymbolAddress((void**)&xh,  g_xh);
    cudaGetSymbolAddress((void**)&yh,  g_yh);
    cudaGetSymbolAddress((void**)&kh,  g_kh);
    cudaGetSymbolAddress((void**)&vh,  g_vh);
    cudaGetSymbolAddress((void**)&t1h, g_t1h);
    cudaGetSymbolAddress((void**)&ffh, g_ffh);
    cudaGetSymbolAddress((void**)&wk,  g_wk);
    cudaGetSymbolAddress((void**)&wv,  g_wv);
    cudaGetSymbolAddress((void**)&wo,  g_wo);
    cudaGetSymbolAddress((void**)&w1,  g_w1);
    cudaGetSymbolAddress((void**)&w2,  g_w2);

    cudaFuncSetAttribute(gemm_h, cudaFuncAttributeMaxDynamicSharedMemorySize,
                         DSMEM_BYTES);
    cudaFuncSetAttribute(flash_attn, cudaFuncAttributeMaxDynamicSharedMemorySize,
                         FL_SMEM);

    add_pos_kernel<<<(Bb*Ss*Dd)/256, 256>>>(q_embed, qa_embed, pos, x, xh, yh);

    for (int l = 0; l < Ll; l++) {
        const float* bkl_ = bk + (long)l*Dd;
        const float* bvl_ = bv + (long)l*Dd;
        const float* bol_ = bo + (long)l*Dd;
        const float* b1l_ = b1 + (long)l*FFf;
        const float* b2l_ = b2 + (long)l*Dd;

        wconv_all<<<(WCONV_TOTAL + 255)/256, 256>>>(
            Wk + (long)l*Dd*Dd, Wv + (long)l*Dd*Dd, Wo + (long)l*Dd*Dd,
            W1 + (long)l*FFf*Dd, W2 + (long)l*Dd*FFf,
            wk, wv, wo, w1, w2);

        dim3 gP (Dd/128,  (Bb*Ss)/128);
        dim3 gF1(FFf/128, (Bb*Ss)/128);
        dim3 gF2(Dd/128,  (Bb*Ss)/128);
        dim3 gFA(Ss/128,  Bb*Hh);

        // K = x @ Wk^T + bk  -> fp16 row-major (q == k)
        gemm_h<<<gP, 256, DSMEM_BYTES>>>(xh, Dd, wk, Dd, bkl_, kh, Dd, Dd, 0);
        // V = y @ Wv^T + bv  -> fp16 row-major (coalesced; flash transposes)
        gemm_h<<<gP, 256, DSMEM_BYTES>>>(yh, Dd, wv, Dd, bvl_, vh, Dd, Dd, 0);
        // fused attention: scores + masked softmax + P@V -> t1h
        flash_attn<<<gFA, 256, FL_SMEM>>>(kh, vh, t1h);
        // t2 = t1 @ Wo^T + bo -> fp16     (launch #6 overall: ncu target)
        gemm_h<<<gP, 256, DSMEM_BYTES>>>(t1h, Dd, wo, Dd, bol_, t2h, Dd, Dd, 0);
        // x = LN(x + t2) -> fp32 + fp16
        ln_res<<<Bb*Ss, 256>>>(x, t2h, ln1g + (long)l*Dd, ln1b + (long)l*Dd, x, xh);
        // ff = relu(x @ W1^T + b1) -> fp16
        gemm_h<<<gF1, 256, DSMEM_BYTES>>>(xh, Dd, w1, Dd, b1l_, ffh, FFf, Dd, 1);
        // t2 = ff @ W2^T + b2 -> fp16
        gemm_h<<<gF2, 256, DSMEM_BYTES>>>(ffh, FFf, w2, FFf, b2l_, t2h, Dd, FFf, 0);
        // x = LN(x + t2); final layer -> d_out (fp32 only)
        float* xout = (l == Ll - 1) ? out : x;
        __half* xhout = (l == Ll - 1) ? nullptr : xh;
        ln_res<<<Bb*Ss, 256>>>(x, t2h, ln2g + (long)l*Dd, ln2b + (long)l*Dd,
                               xout, xhout);
    }
}